// round 4
// baseline (speedup 1.0000x reference)
#include <cuda_runtime.h>
#include <cuda_bf16.h>
#include <cstdint>

#define NB 4
#define NC 256
#define NN 4096
#define TI 64
#define TJ 32
#define NSTEPS (NN / TJ)

// ---------------- device scratch (allocation-free) ----------------
__device__ unsigned short g_q[(size_t)NB * NN * 64];     // [b][n][32hi|32lo]
__device__ unsigned short g_k[(size_t)NB * NN * 64];
__device__ unsigned short g_vh[(size_t)NB * NC * NN];    // [b][c][n] hi
__device__ unsigned short g_vl[(size_t)NB * NC * NN];    // lo

// ---------------- SMEM layout for attn (bytes) ----------------
#define SQ 0                    // 64 rows x 128B = 8192
#define SK 8192                 // + bf*4096 (32 rows x 128B)
#define SP 16384                // 64 rows x 128B (P exchange)
#define SV 24576                // + bf*32768 ; 256 c-rows x (32j hi|32j lo)=128B
#define SL (24576 + 65536)      // lsum: 2 x 64 floats = 512B
#define SMEMB (SL + 512)        // 90624

// ---------------- PTX helpers ----------------
__device__ __forceinline__ uint32_t smem_u32(const void* p) {
    uint32_t a;
    asm("{ .reg .u64 t; cvta.to.shared.u64 t, %1; cvt.u32.u64 %0, t; }" : "=r"(a) : "l"(p));
    return a;
}
__device__ __forceinline__ void cp16(uint32_t dst, const void* src) {
    asm volatile("cp.async.cg.shared.global [%0], [%1], 16;" :: "r"(dst), "l"(src));
}
__device__ __forceinline__ void cp_commit() { asm volatile("cp.async.commit_group;" ::: "memory"); }
__device__ __forceinline__ void cp_wait0()  { asm volatile("cp.async.wait_group 0;" ::: "memory"); }

__device__ __forceinline__ void ldsm4(uint32_t* r, uint32_t a) {
    asm volatile("ldmatrix.sync.aligned.m8n8.x4.shared.b16 {%0,%1,%2,%3}, [%4];"
        : "=r"(r[0]), "=r"(r[1]), "=r"(r[2]), "=r"(r[3]) : "r"(a));
}
__device__ __forceinline__ void ldsm4t(uint32_t* r, uint32_t a) {
    asm volatile("ldmatrix.sync.aligned.m8n8.x4.trans.shared.b16 {%0,%1,%2,%3}, [%4];"
        : "=r"(r[0]), "=r"(r[1]), "=r"(r[2]), "=r"(r[3]) : "r"(a));
}
__device__ __forceinline__ void mma16816(float* d, const uint32_t* a, uint32_t b0, uint32_t b1) {
    asm volatile("mma.sync.aligned.m16n8k16.row.col.f32.bf16.bf16.f32 "
        "{%0,%1,%2,%3}, {%4,%5,%6,%7}, {%8,%9}, {%0,%1,%2,%3};"
        : "+f"(d[0]), "+f"(d[1]), "+f"(d[2]), "+f"(d[3])
        : "r"(a[0]), "r"(a[1]), "r"(a[2]), "r"(a[3]), "r"(b0), "r"(b1));
}
// pack: first arg -> low half, second -> high half (validated in round 3)
__device__ __forceinline__ uint32_t packbf(float lo, float hi) {
    uint32_t r;
    asm("cvt.rn.bf16x2.f32 %0, %1, %2;" : "=r"(r) : "f"(hi), "f"(lo));
    return r;
}
__device__ __forceinline__ unsigned short bfh(float v) {
    __nv_bfloat16 h = __float2bfloat16(v);
    return *reinterpret_cast<unsigned short*>(&h);
}
__device__ __forceinline__ float bff(unsigned short u) {
    return __uint_as_float(((uint32_t)u) << 16);
}

// ---------------- attn K/V tile prefetch (256 threads) ----------------
__device__ __forceinline__ void prefetch_kv(uint32_t sb, int bf, int b, int j0, int t) {
    {   // K: 32 rows x 8 chunks
        int row = t >> 3, ch = t & 7;
        cp16(sb + SK + bf * 4096 + row * 128 + ((ch ^ (row & 7)) << 4),
             g_k + ((size_t)(b * NN + j0 + row)) * 64 + ch * 8);
    }
    // V: 256 c-rows, hi chunks 0-3, lo chunks 4-7 (32 j's per plane)
    #pragma unroll
    for (int k = 0; k < 4; k++) {
        int idx = t + 256 * k;
        int c = idx >> 2, m = idx & 3;
        cp16(sb + SV + bf * 32768 + c * 128 + ((m ^ (c & 7)) << 4),
             g_vh + ((size_t)(b * NC + c)) * NN + j0 + m * 8);
    }
    #pragma unroll
    for (int k = 0; k < 4; k++) {
        int idx = t + 256 * k;
        int c = idx >> 2, m = idx & 3;
        cp16(sb + SV + bf * 32768 + c * 128 + (((m + 4) ^ (c & 7)) << 4),
             g_vl + ((size_t)(b * NC + c)) * NN + j0 + m * 8);
    }
}

// =====================================================================
// bf16 mma.sync flash attention, occ-2 version.
// 8 warps: wi = w&3 (16-row group), wc = w>>2 (j-half for QK, c-half for PV)
// P exchanged between warp pairs through smem (hi/lo bf16).
// =====================================================================
__global__ __launch_bounds__(256, 2) void attn_kernel(
    const float* __restrict__ x, float* __restrict__ out)
{
    extern __shared__ char smem[];
    const uint32_t sb = smem_u32(smem);
    const int t = threadIdx.x, lane = t & 31, w = t >> 5;
    const int wi = w & 3, wc = w >> 2;
    const int b = blockIdx.y, i0 = blockIdx.x * TI;
    const int rr = lane >> 2, qd = lane & 3;
    const int l7 = lane & 7, lm8 = ((lane >> 3) & 1) * 8, lhi = lane >> 4, lm4 = lane >> 3;

    // ---- prefetch Q (64 rows x 8 chunks) + first K/V tile ----
    #pragma unroll
    for (int k = 0; k < 2; k++) {
        int idx = t + 256 * k;
        int row = idx >> 3, ch = idx & 7;
        cp16(sb + SQ + row * 128 + ((ch ^ (row & 7)) << 4),
             g_q + ((size_t)(b * NN + i0 + row)) * 64 + ch * 8);
    }
    prefetch_kv(sb, 0, b, 0, t);
    cp_commit();
    cp_wait0();
    __syncthreads();

    // ---- resident Q fragments (hi/lo, 2 k-chunks) ----
    uint32_t qh[2][4], ql[2][4];
    #pragma unroll
    for (int kc = 0; kc < 2; kc++) {
        int row = wi * 16 + l7 + lm8;
        int chh = 2 * kc + lhi;
        ldsm4(qh[kc], sb + SQ + row * 128 + ((chh ^ (row & 7)) << 4));
        ldsm4(ql[kc], sb + SQ + row * 128 + (((chh + 4) ^ (row & 7)) << 4));
    }

    float O[16][4];
    #pragma unroll
    for (int i = 0; i < 16; i++)
        #pragma unroll
        for (int j = 0; j < 4; j++) O[i][j] = 0.f;
    float rs0 = 0.f, rs1 = 0.f;

    for (int st = 0; st < NSTEPS; st++) {
        const int bf = st & 1;
        if (st > 0) { cp_wait0(); __syncthreads(); }
        if (st + 1 < NSTEPS) { prefetch_kv(sb, bf ^ 1, b, (st + 1) * TJ, t); cp_commit(); }

        const uint32_t kbase = sb + SK + bf * 4096;
        const uint32_t vbase = sb + SV + bf * 32768;

        // ---- S[16 rows][16 j of half wc] ----
        float S[2][4];
        #pragma unroll
        for (int h = 0; h < 2; h++) {
            S[h][0] = S[h][1] = S[h][2] = S[h][3] = 0.f;
            int krow = wc * 16 + h * 8 + l7;
            int swk = krow & 7;
            uint32_t kh4[4], kl4[4];
            ldsm4(kh4, kbase + krow * 128 + ((lm4 ^ swk) << 4));
            ldsm4(kl4, kbase + krow * 128 + (((lm4 + 4) ^ swk) << 4));
            mma16816(S[h], qh[0], kh4[0], kh4[1]);
            mma16816(S[h], qh[1], kh4[2], kh4[3]);
            mma16816(S[h], qh[0], kl4[0], kl4[1]);
            mma16816(S[h], qh[1], kl4[2], kl4[3]);
            mma16816(S[h], ql[0], kh4[0], kh4[1]);
            mma16816(S[h], ql[1], kh4[2], kh4[3]);
        }

        // ---- exp + hi/lo pack + store P to exchange smem ----
        #pragma unroll
        for (int h = 0; h < 2; h++) {
            float e0 = __expf(S[h][0]), e1 = __expf(S[h][1]);
            float e2 = __expf(S[h][2]), e3 = __expf(S[h][3]);
            rs0 += e0 + e1;
            rs1 += e2 + e3;
            uint32_t h01 = packbf(e0, e1), h23 = packbf(e2, e3);
            uint32_t l01 = packbf(e0 - __uint_as_float(h01 << 16),
                                  e1 - __uint_as_float(h01 & 0xffff0000u));
            uint32_t l23 = packbf(e2 - __uint_as_float(h23 << 16),
                                  e3 - __uint_as_float(h23 & 0xffff0000u));
            int chh = wc * 2 + h;          // hi chunk ; lo = +4
            int r0 = wi * 16 + rr, r1 = r0 + 8;
            uint32_t a0 = sb + SP + r0 * 128 + qd * 4;
            uint32_t a1 = sb + SP + r1 * 128 + qd * 4;
            *(uint32_t*)(smem + (a0 - sb) + ((chh ^ (r0 & 7)) << 4)) = h01;
            *(uint32_t*)(smem + (a0 - sb) + (((chh + 4) ^ (r0 & 7)) << 4)) = l01;
            *(uint32_t*)(smem + (a1 - sb) + ((chh ^ (r1 & 7)) << 4)) = h23;
            *(uint32_t*)(smem + (a1 - sb) + (((chh + 4) ^ (r1 & 7)) << 4)) = l23;
        }
        __syncthreads();

        // ---- reload full-j P fragments ----
        uint32_t pah[2][4], pal[2][4];
        {
            int row = wi * 16 + l7 + lm8;
            int swp = row & 7;
            #pragma unroll
            for (int kc = 0; kc < 2; kc++) {
                int chh = kc * 2 + lhi;
                ldsm4(pah[kc], sb + SP + row * 128 + ((chh ^ swp) << 4));
                ldsm4(pal[kc], sb + SP + row * 128 + (((chh + 4) ^ swp) << 4));
            }
        }

        // ---- O += P @ V over channel half wc (16 c-blocks of 8) ----
        #pragma unroll
        for (int cb = 0; cb < 16; cb++) {
            int crow = wc * 128 + cb * 8 + l7;
            int swv = crow & 7;
            uint32_t vh4[4], vl4[4];
            ldsm4(vh4, vbase + crow * 128 + ((lm4 ^ swv) << 4));
            ldsm4(vl4, vbase + crow * 128 + (((lm4 + 4) ^ swv) << 4));
            mma16816(O[cb], pah[0], vh4[0], vh4[1]);
            mma16816(O[cb], pah[1], vh4[2], vh4[3]);
            mma16816(O[cb], pal[0], vh4[0], vh4[1]);
            mma16816(O[cb], pal[1], vh4[2], vh4[3]);
            mma16816(O[cb], pah[0], vl4[0], vl4[1]);
            mma16816(O[cb], pah[1], vl4[2], vl4[3]);
        }
    }

    // ---- reduce row sums across j-halves ----
    rs0 += __shfl_xor_sync(0xffffffffu, rs0, 1);
    rs0 += __shfl_xor_sync(0xffffffffu, rs0, 2);
    rs1 += __shfl_xor_sync(0xffffffffu, rs1, 1);
    rs1 += __shfl_xor_sync(0xffffffffu, rs1, 2);
    float* lsum = (float*)(smem + SL);
    __syncthreads();
    if (qd == 0) {
        lsum[wc * 64 + wi * 16 + rr] = rs0;
        lsum[wc * 64 + wi * 16 + rr + 8] = rs1;
    }
    __syncthreads();
    const int n_lo = i0 + wi * 16 + rr;
    const float li0 = 1.0f / (lsum[wi * 16 + rr] + lsum[64 + wi * 16 + rr]);
    const float li1 = 1.0f / (lsum[wi * 16 + rr + 8] + lsum[64 + wi * 16 + rr + 8]);

    // ---- epilogue: O/l + residual ----
    #pragma unroll
    for (int cb = 0; cb < 16; cb++) {
        int c = wc * 128 + cb * 8 + qd * 2;
        size_t g = ((size_t)b * NC + c) * NN + n_lo;
        out[g]          = O[cb][0] * li0 + x[g];
        out[g + NN]     = O[cb][1] * li0 + x[g + NN];
        out[g + 8]      = O[cb][2] * li1 + x[g + 8];
        out[g + 8 + NN] = O[cb][3] * li1 + x[g + 8 + NN];
    }
}

// =====================================================================
// Projection Q/K: [b][n][32hi|32lo] bf16 (scalar fp32 GEMM, small)
// =====================================================================
__global__ __launch_bounds__(256) void proj_qk(
    const float* __restrict__ x, const float* __restrict__ W,
    const float* __restrict__ bias, unsigned short* __restrict__ o64)
{
    __shared__ float xs[32][64];
    __shared__ float ws[32][33];
    const int b  = blockIdx.z;
    const int n0 = blockIdx.x * 64;
    const int t  = threadIdx.x;
    const int go = t & 7, gn = t >> 3;

    float acc[4][2];
    #pragma unroll
    for (int r = 0; r < 4; r++) { acc[r][0] = 0.f; acc[r][1] = 0.f; }

    const float* xb = x + (size_t)b * NC * NN + n0;
    for (int c0 = 0; c0 < NC; c0 += 32) {
        {
            int cc = t >> 3, nn = (t & 7) * 8;
            const float* src = xb + (size_t)(c0 + cc) * NN + nn;
            *(float4*)&xs[cc][nn]     = *(const float4*)src;
            *(float4*)&xs[cc][nn + 4] = *(const float4*)(src + 4);
        }
        {
            int o = t >> 3, c4 = (t & 7) * 4;
            const float* src = W + (size_t)o * NC + c0 + c4;
            #pragma unroll
            for (int k = 0; k < 4; k++) ws[o][c4 + k] = src[k];
        }
        __syncthreads();
        #pragma unroll
        for (int cc = 0; cc < 32; cc++) {
            float x0 = xs[cc][gn * 2], x1 = xs[cc][gn * 2 + 1];
            #pragma unroll
            for (int r = 0; r < 4; r++) {
                float wv = ws[go * 4 + r][cc];
                acc[r][0] = fmaf(wv, x0, acc[r][0]);
                acc[r][1] = fmaf(wv, x1, acc[r][1]);
            }
        }
        __syncthreads();
    }

    float bs[4];
    #pragma unroll
    for (int r = 0; r < 4; r++) bs[r] = bias[go * 4 + r];
    #pragma unroll
    for (int i = 0; i < 2; i++) {
        int n = n0 + gn * 2 + i;
        unsigned short h[4], l[4];
        #pragma unroll
        for (int r = 0; r < 4; r++) {
            float v = acc[r][i] + bs[r];
            h[r] = bfh(v);
            l[r] = bfh(v - bff(h[r]));
        }
        size_t base = ((size_t)(b * NN + n)) * 64 + go * 4;
        *(ushort4*)&o64[base]      = make_ushort4(h[0], h[1], h[2], h[3]);
        *(ushort4*)&o64[base + 32] = make_ushort4(l[0], l[1], l[2], l[3]);
    }
}

// =====================================================================
// Projection V via mma.sync: D[c 128][n 128] = Wv @ x  (3-product bf16)
// Output: g_vh/g_vl [b][c][n]
// =====================================================================
__global__ __launch_bounds__(256) void proj_v_mma(
    const float* __restrict__ x, const float* __restrict__ W,
    const float* __restrict__ bias,
    unsigned short* __restrict__ vh, unsigned short* __restrict__ vl)
{
    __shared__ char pvs[32768];
    const uint32_t sb = smem_u32(pvs);
    const uint32_t SA = 0, SB = 16384;   // SA: Wv [c128][32hi|32lo]; SB: x [k32][128n hi|lo]
    const int t = threadIdx.x, lane = t & 31, w = t >> 5;
    const int n0 = blockIdx.x * 128, c0 = blockIdx.y * 128, b = blockIdx.z;
    const int rr = lane >> 2, qd = lane & 3;
    const int l7 = lane & 7, lm8 = ((lane >> 3) & 1) * 8, lhi = lane >> 4;

    float O[16][4];
    #pragma unroll
    for (int i = 0; i < 16; i++)
        #pragma unroll
        for (int j = 0; j < 4; j++) O[i][j] = 0.f;

    for (int k0 = 0; k0 < NC; k0 += 32) {
        // ---- load + convert Wv tile [c 128][k 32] ----
        {
            int c = t >> 1, ks = (t & 1) * 16;
            const float* src = W + (size_t)(c0 + c) * NC + k0 + ks;
            int sw = c & 7;
            #pragma unroll
            for (int p = 0; p < 8; p++) {
                float v0 = src[p * 2], v1 = src[p * 2 + 1];
                uint32_t hp = packbf(v0, v1);
                uint32_t lp = packbf(v0 - __uint_as_float(hp << 16),
                                     v1 - __uint_as_float(hp & 0xffff0000u));
                int kk = ks + p * 2;
                int chh = kk >> 3, off = (kk & 7) * 2;
                *(uint32_t*)(pvs + SA + c * 128 + ((chh ^ sw) << 4) + off) = hp;
                *(uint32_t*)(pvs + SA + c * 128 + (((chh + 4) ^ sw) << 4) + off) = lp;
            }
        }
        // ---- load + convert x tile [k 32][n 128] ----
        {
            int k = t >> 3, ns = (t & 7) * 16;
            const float* src = x + ((size_t)(b * NC + k0 + k)) * NN + n0 + ns;
            #pragma unroll
            for (int p = 0; p < 8; p++) {
                float v0 = src[p * 2], v1 = src[p * 2 + 1];
                uint32_t hp = packbf(v0, v1);
                uint32_t lp = packbf(v0 - __uint_as_float(hp << 16),
                                     v1 - __uint_as_float(hp & 0xffff0000u));
                int nn = ns + p * 2;
                int chh = nn >> 3, off = (nn & 7) * 2;
                *(uint32_t*)(pvs + SB + k * 512 + (((chh & 24) | ((chh ^ k) & 7)) << 4) + off) = hp;
                int chl = chh + 16;
                *(uint32_t*)(pvs + SB + k * 512 + (((chl & 24) | ((chl ^ k) & 7)) << 4) + off) = lp;
            }
        }
        __syncthreads();

        // ---- A frags (Wv rows w*16..) ----
        uint32_t ah[2][4], al[2][4];
        {
            int row = w * 16 + l7 + lm8;
            int sw = row & 7;
            #pragma unroll
            for (int kc = 0; kc < 2; kc++) {
                int chh = kc * 2 + lhi;
                ldsm4(ah[kc], sb + SA + row * 128 + ((chh ^ sw) << 4));
                ldsm4(al[kc], sb + SA + row * 128 + (((chh + 4) ^ sw) << 4));
            }
        }
        // ---- B frags (x^T via trans ldmatrix) + MMA ----
        #pragma unroll
        for (int kc = 0; kc < 2; kc++) {
            int vrow = kc * 16 + l7 + lm8;
            uint32_t vroff = sb + SB + vrow * 512;
            int swv = vrow & 7;
            #pragma unroll
            for (int vb = 0; vb < 8; vb++) {
                int ch = vb * 2 + lhi;
                uint32_t xh4[4], xl4[4];
                ldsm4t(xh4, vroff + (((ch & 24) | ((ch ^ swv) & 7)) << 4));
                int chl = ch + 16;
                ldsm4t(xl4, vroff + (((chl & 24) | ((chl ^ swv) & 7)) << 4));
                mma16816(O[2 * vb],     ah[kc], xh4[0], xh4[1]);
                mma16816(O[2 * vb + 1], ah[kc], xh4[2], xh4[3]);
                mma16816(O[2 * vb],     al[kc], xh4[0], xh4[1]);
                mma16816(O[2 * vb + 1], al[kc], xh4[2], xh4[3]);
                mma16816(O[2 * vb],     ah[kc], xl4[0], xl4[1]);
                mma16816(O[2 * vb + 1], ah[kc], xl4[2], xl4[3]);
            }
        }
        __syncthreads();
    }

    // ---- epilogue: +bias, split hi/lo, store [b][c][n] ----
    const int c_lo = c0 + w * 16 + rr;
    const float b0 = bias[c_lo], b1 = bias[c_lo + 8];
    #pragma unroll
    for (int nb = 0; nb < 16; nb++) {
        int n = n0 + nb * 8 + qd * 2;
        float v0 = O[nb][0] + b0, v1 = O[nb][1] + b0;
        float u0 = O[nb][2] + b1, u1 = O[nb][3] + b1;
        uint32_t hp0 = packbf(v0, v1);
        uint32_t lp0 = packbf(v0 - __uint_as_float(hp0 << 16),
                              v1 - __uint_as_float(hp0 & 0xffff0000u));
        uint32_t hp1 = packbf(u0, u1);
        uint32_t lp1 = packbf(u0 - __uint_as_float(hp1 << 16),
                              u1 - __uint_as_float(hp1 & 0xffff0000u));
        size_t g0 = ((size_t)(b * NC + c_lo)) * NN + n;
        size_t g1 = ((size_t)(b * NC + c_lo + 8)) * NN + n;
        *(uint32_t*)&vh[g0] = hp0;
        *(uint32_t*)&vl[g0] = lp0;
        *(uint32_t*)&vh[g1] = hp1;
        *(uint32_t*)&vl[g1] = lp1;
    }
}

// =====================================================================
extern "C" void kernel_launch(void* const* d_in, const int* in_sizes, int n_in,
                              void* d_out, int out_size)
{
    const float* x  = (const float*)d_in[0];
    const float* Wq = (const float*)d_in[1];
    const float* bq = (const float*)d_in[2];
    const float* Wk = (const float*)d_in[3];
    const float* bk = (const float*)d_in[4];
    const float* Wv = (const float*)d_in[5];
    const float* bv = (const float*)d_in[6];
    float* out = (float*)d_out;

    unsigned short *pq, *pk, *pvh, *pvl;
    cudaGetSymbolAddress((void**)&pq,  g_q);
    cudaGetSymbolAddress((void**)&pk,  g_k);
    cudaGetSymbolAddress((void**)&pvh, g_vh);
    cudaGetSymbolAddress((void**)&pvl, g_vl);

    cudaFuncSetAttribute(attn_kernel, cudaFuncAttributeMaxDynamicSharedMemorySize, SMEMB);

    dim3 blk(256);
    proj_qk<<<dim3(NN / 64, 1, NB), blk>>>(x, Wq, bq, pq);
    proj_qk<<<dim3(NN / 64, 1, NB), blk>>>(x, Wk, bk, pk);
    proj_v_mma<<<dim3(NN / 128, NC / 128, NB), blk>>>(x, Wv, bv, pvh, pvl);
    attn_kernel<<<dim3(NN / TI, NB), blk, SMEMB>>>(x, out);
}

// round 5
// speedup vs baseline: 1.4517x; 1.4517x over previous
#include <cuda_runtime.h>
#include <cuda_bf16.h>
#include <cstdint>

#define NB 4
#define NC 256
#define NN 4096
#define TI 128
#define TJ 64
#define NSTEPS (NN / TJ)

// ---------------- device scratch (allocation-free) ----------------
__device__ unsigned short g_q[(size_t)NB * NN * 64];     // [b][n][32hi|32lo]
__device__ unsigned short g_k[(size_t)NB * NN * 64];
__device__ unsigned short g_vh[(size_t)NB * NN * 256];   // [b][n][c] hi only

// ---------------- SMEM layout (bytes) ----------------
#define SQ 0                       // 128 rows x 128B = 16384
#define SK 16384                   // + bf*8192 (64 rows x 128B)
#define SV 32768                   // + bf*32768 ; 64 j-rows x 512B (hi only)
#define SMEMB (32768 + 2 * 32768)  // 98304

// ---------------- PTX helpers ----------------
__device__ __forceinline__ uint32_t smem_u32(const void* p) {
    uint32_t a;
    asm("{ .reg .u64 t; cvta.to.shared.u64 t, %1; cvt.u32.u64 %0, t; }" : "=r"(a) : "l"(p));
    return a;
}
__device__ __forceinline__ void cp16(uint32_t dst, const void* src) {
    asm volatile("cp.async.cg.shared.global [%0], [%1], 16;" :: "r"(dst), "l"(src));
}
__device__ __forceinline__ void cp_commit() { asm volatile("cp.async.commit_group;" ::: "memory"); }
__device__ __forceinline__ void cp_wait0()  { asm volatile("cp.async.wait_group 0;" ::: "memory"); }

__device__ __forceinline__ void ldsm4(uint32_t* r, uint32_t a) {
    asm volatile("ldmatrix.sync.aligned.m8n8.x4.shared.b16 {%0,%1,%2,%3}, [%4];"
        : "=r"(r[0]), "=r"(r[1]), "=r"(r[2]), "=r"(r[3]) : "r"(a));
}
__device__ __forceinline__ void ldsm4t(uint32_t* r, uint32_t a) {
    asm volatile("ldmatrix.sync.aligned.m8n8.x4.trans.shared.b16 {%0,%1,%2,%3}, [%4];"
        : "=r"(r[0]), "=r"(r[1]), "=r"(r[2]), "=r"(r[3]) : "r"(a));
}
__device__ __forceinline__ void mma16816(float* d, const uint32_t* a, uint32_t b0, uint32_t b1) {
    asm volatile("mma.sync.aligned.m16n8k16.row.col.f32.bf16.bf16.f32 "
        "{%0,%1,%2,%3}, {%4,%5,%6,%7}, {%8,%9}, {%0,%1,%2,%3};"
        : "+f"(d[0]), "+f"(d[1]), "+f"(d[2]), "+f"(d[3])
        : "r"(a[0]), "r"(a[1]), "r"(a[2]), "r"(a[3]), "r"(b0), "r"(b1));
}
// pack: first arg -> low half, second -> high half (validated round 3)
__device__ __forceinline__ uint32_t packbf(float lo, float hi) {
    uint32_t r;
    asm("cvt.rn.bf16x2.f32 %0, %1, %2;" : "=r"(r) : "f"(hi), "f"(lo));
    return r;
}
__device__ __forceinline__ unsigned short bfh(float v) {
    __nv_bfloat16 h = __float2bfloat16(v);
    return *reinterpret_cast<unsigned short*>(&h);
}
__device__ __forceinline__ float bff(unsigned short u) {
    return __uint_as_float(((uint32_t)u) << 16);
}

// ---------------- K/V tile prefetch (256 threads) ----------------
__device__ __forceinline__ void prefetch_kv(uint32_t sb, int bf, int b, int j0, int t) {
    const unsigned short* ks = g_k + ((size_t)(b * NN + j0)) * 64;
    #pragma unroll
    for (int kk = 0; kk < 2; kk++) {
        int idx = t + kk * 256;
        int row = idx >> 3, ch = idx & 7;
        cp16(sb + SK + bf * 8192 + row * 128 + ((ch ^ (row & 7)) << 4),
             ks + (size_t)row * 64 + ch * 8);
    }
    const unsigned short* hs = g_vh + ((size_t)(b * NN + j0)) * 256;
    #pragma unroll
    for (int kk = 0; kk < 8; kk++) {
        int idx = t + kk * 256;
        int row = idx >> 5, ch = idx & 31;
        uint32_t off = row * 512 + (((ch & 24) | ((ch ^ row) & 7)) << 4);
        cp16(sb + SV + bf * 32768 + off, hs + (size_t)row * 256 + ch * 8);
    }
}

// =====================================================================
// bf16 mma.sync flash attention (Q/K hi-lo split, V bf16) + residual
// 8 warps x 16 rows = 128 query rows, full 64-j tile per warp.
// =====================================================================
__global__ __launch_bounds__(256, 1) void attn_kernel(
    const float* __restrict__ x, float* __restrict__ out)
{
    extern __shared__ char smem[];
    const uint32_t sb = smem_u32(smem);
    const int t = threadIdx.x, lane = t & 31, w = t >> 5;
    const int b = blockIdx.y, i0 = blockIdx.x * TI;
    const int rr = lane >> 2, qd = lane & 3;
    const int l7 = lane & 7, lm8 = ((lane >> 3) & 1) * 8, lhi = lane >> 4, lm4 = lane >> 3;

    // ---- prefetch Q tile + first K/V tile ----
    {
        const unsigned short* qs = g_q + ((size_t)(b * NN + i0)) * 64;
        #pragma unroll
        for (int kk = 0; kk < 4; kk++) {
            int idx = t + kk * 256;
            int row = idx >> 3, ch = idx & 7;
            cp16(sb + SQ + row * 128 + ((ch ^ (row & 7)) << 4),
                 qs + (size_t)row * 64 + ch * 8);
        }
        prefetch_kv(sb, 0, b, 0, t);
        cp_commit();
    }
    cp_wait0();
    __syncthreads();

    // ---- resident Q fragments (hi/lo, 2 k-chunks) ----
    uint32_t qh[2][4], ql[2][4];
    #pragma unroll
    for (int kc = 0; kc < 2; kc++) {
        int row = w * 16 + l7 + lm8;
        int chh = 2 * kc + lhi;
        ldsm4(qh[kc], sb + SQ + row * 128 + ((chh ^ (row & 7)) << 4));
        ldsm4(ql[kc], sb + SQ + row * 128 + (((chh + 4) ^ (row & 7)) << 4));
    }

    float O[32][4];
    #pragma unroll
    for (int i = 0; i < 32; i++)
        #pragma unroll
        for (int j = 0; j < 4; j++) O[i][j] = 0.f;
    float rs0 = 0.f, rs1 = 0.f;

    for (int st = 0; st < NSTEPS; st++) {
        const int bf = st & 1;
        if (st > 0) { cp_wait0(); __syncthreads(); }
        if (st + 1 < NSTEPS) { prefetch_kv(sb, bf ^ 1, b, (st + 1) * TJ, t); cp_commit(); }

        const uint32_t kbase = sb + SK + bf * 8192;
        const uint32_t vbase = sb + SV + bf * 32768;

        #pragma unroll
        for (int kc = 0; kc < 4; kc++) {
            // ---- S for j-blocks 2kc, 2kc+1 ----
            float S[2][4];
            #pragma unroll
            for (int h = 0; h < 2; h++) {
                S[h][0] = S[h][1] = S[h][2] = S[h][3] = 0.f;
                int krow = (2 * kc + h) * 8 + l7;
                int swk = (krow & 7);
                uint32_t kh4[4], kl4[4];
                ldsm4(kh4, kbase + krow * 128 + ((lm4 ^ swk) << 4));
                ldsm4(kl4, kbase + krow * 128 + (((lm4 + 4) ^ swk) << 4));
                mma16816(S[h], qh[0], kh4[0], kh4[1]);
                mma16816(S[h], qh[1], kh4[2], kh4[3]);
                mma16816(S[h], qh[0], kl4[0], kl4[1]);
                mma16816(S[h], qh[1], kl4[2], kl4[3]);
                mma16816(S[h], ql[0], kh4[0], kh4[1]);
                mma16816(S[h], ql[1], kh4[2], kh4[3]);
            }

            // ---- exp (no max-sub) + bf16 hi/lo pack ----
            uint32_t pah[4], pal[4];
            #pragma unroll
            for (int h = 0; h < 2; h++) {
                float e0 = __expf(S[h][0]), e1 = __expf(S[h][1]);
                float e2 = __expf(S[h][2]), e3 = __expf(S[h][3]);
                rs0 += e0 + e1;
                rs1 += e2 + e3;
                uint32_t h01 = packbf(e0, e1), h23 = packbf(e2, e3);
                pah[h * 2] = h01; pah[h * 2 + 1] = h23;
                float f0 = __uint_as_float(h01 << 16), f1 = __uint_as_float(h01 & 0xffff0000u);
                float f2 = __uint_as_float(h23 << 16), f3 = __uint_as_float(h23 & 0xffff0000u);
                pal[h * 2]     = packbf(e0 - f0, e1 - f1);
                pal[h * 2 + 1] = packbf(e2 - f2, e3 - f3);
            }

            // ---- O += (Phi+Plo) @ Vhi over all 32 channel-blocks ----
            int vrow = kc * 16 + l7 + lm8;
            uint32_t vroff = vbase + vrow * 512;
            int swv = (vrow & 7);
            #pragma unroll
            for (int vb = 0; vb < 16; vb++) {
                int ch = vb * 2 + lhi;
                uint32_t a = vroff + ((((ch & 24) | ((ch ^ swv) & 7))) << 4);
                uint32_t vh4[4];
                ldsm4t(vh4, a);
                mma16816(O[2 * vb],     pah, vh4[0], vh4[1]);
                mma16816(O[2 * vb + 1], pah, vh4[2], vh4[3]);
                mma16816(O[2 * vb],     pal, vh4[0], vh4[1]);
                mma16816(O[2 * vb + 1], pal, vh4[2], vh4[3]);
            }
        }
    }

    // ---- row-sum reduce + epilogue (O/l + residual) ----
    rs0 += __shfl_xor_sync(0xffffffffu, rs0, 1);
    rs0 += __shfl_xor_sync(0xffffffffu, rs0, 2);
    rs1 += __shfl_xor_sync(0xffffffffu, rs1, 1);
    rs1 += __shfl_xor_sync(0xffffffffu, rs1, 2);
    const float li0 = 1.0f / rs0, li1 = 1.0f / rs1;

    const int ng = i0 + w * 16 + rr;
    #pragma unroll
    for (int nb = 0; nb < 32; nb++) {
        int c = nb * 8 + qd * 2;
        size_t g = ((size_t)b * NC + c) * NN + ng;
        out[g]          = O[nb][0] * li0 + x[g];
        out[g + NN]     = O[nb][1] * li0 + x[g + NN];
        out[g + 8]      = O[nb][2] * li1 + x[g + 8];
        out[g + 8 + NN] = O[nb][3] * li1 + x[g + 8 + NN];
    }
}

// =====================================================================
// Fused Q+K projection: reads x once, writes both [b][n][32hi|32lo]
// =====================================================================
__global__ __launch_bounds__(256) void proj_qk2(
    const float* __restrict__ x,
    const float* __restrict__ Wq, const float* __restrict__ bq,
    const float* __restrict__ Wk, const float* __restrict__ bk,
    unsigned short* __restrict__ oq, unsigned short* __restrict__ ok)
{
    __shared__ float xs[32][64];
    __shared__ float wqs[32][33];
    __shared__ float wks[32][33];
    const int b  = blockIdx.z;
    const int n0 = blockIdx.x * 64;
    const int t  = threadIdx.x;
    const int go = t & 7, gn = t >> 3;

    float aq[4][2], ak[4][2];
    #pragma unroll
    for (int r = 0; r < 4; r++) {
        aq[r][0] = aq[r][1] = 0.f;
        ak[r][0] = ak[r][1] = 0.f;
    }

    const float* xb = x + (size_t)b * NC * NN + n0;
    for (int c0 = 0; c0 < NC; c0 += 32) {
        {
            int cc = t >> 3, nn = (t & 7) * 8;
            const float* src = xb + (size_t)(c0 + cc) * NN + nn;
            *(float4*)&xs[cc][nn]     = *(const float4*)src;
            *(float4*)&xs[cc][nn + 4] = *(const float4*)(src + 4);
        }
        {
            int o = t >> 3, c4 = (t & 7) * 4;
            const float* sq = Wq + (size_t)o * NC + c0 + c4;
            const float* sk = Wk + (size_t)o * NC + c0 + c4;
            #pragma unroll
            for (int k = 0; k < 4; k++) { wqs[o][c4 + k] = sq[k]; wks[o][c4 + k] = sk[k]; }
        }
        __syncthreads();
        #pragma unroll
        for (int cc = 0; cc < 32; cc++) {
            float x0 = xs[cc][gn * 2], x1 = xs[cc][gn * 2 + 1];
            #pragma unroll
            for (int r = 0; r < 4; r++) {
                float wv = wqs[go * 4 + r][cc];
                aq[r][0] = fmaf(wv, x0, aq[r][0]);
                aq[r][1] = fmaf(wv, x1, aq[r][1]);
                float wk2 = wks[go * 4 + r][cc];
                ak[r][0] = fmaf(wk2, x0, ak[r][0]);
                ak[r][1] = fmaf(wk2, x1, ak[r][1]);
            }
        }
        __syncthreads();
    }

    float bsq[4], bsk[4];
    #pragma unroll
    for (int r = 0; r < 4; r++) { bsq[r] = bq[go * 4 + r]; bsk[r] = bk[go * 4 + r]; }
    #pragma unroll
    for (int i = 0; i < 2; i++) {
        int n = n0 + gn * 2 + i;
        size_t base = ((size_t)(b * NN + n)) * 64 + go * 4;
        unsigned short h[4], l[4];
        #pragma unroll
        for (int r = 0; r < 4; r++) {
            float v = aq[r][i] + bsq[r];
            h[r] = bfh(v);
            l[r] = bfh(v - bff(h[r]));
        }
        *(ushort4*)&oq[base]      = make_ushort4(h[0], h[1], h[2], h[3]);
        *(ushort4*)&oq[base + 32] = make_ushort4(l[0], l[1], l[2], l[3]);
        #pragma unroll
        for (int r = 0; r < 4; r++) {
            float v = ak[r][i] + bsk[r];
            h[r] = bfh(v);
            l[r] = bfh(v - bff(h[r]));
        }
        *(ushort4*)&ok[base]      = make_ushort4(h[0], h[1], h[2], h[3]);
        *(ushort4*)&ok[base + 32] = make_ushort4(l[0], l[1], l[2], l[3]);
    }
}

// =====================================================================
// Projection V: vh [b][n][256] bf16 (hi only)
// =====================================================================
__global__ __launch_bounds__(256) void proj_v(
    const float* __restrict__ x, const float* __restrict__ W,
    const float* __restrict__ bias, unsigned short* __restrict__ vh)
{
    __shared__ float xs[32][64];
    __shared__ float ws[64][33];
    const int b  = blockIdx.z;
    const int n0 = blockIdx.x * 64;
    const int o0 = blockIdx.y * 64;
    const int t  = threadIdx.x;
    const int gn = t & 15, go = t >> 4;

    float acc[4][4];
    #pragma unroll
    for (int r = 0; r < 4; r++)
        #pragma unroll
        for (int i = 0; i < 4; i++) acc[r][i] = 0.f;

    const float* xb = x + (size_t)b * NC * NN + n0;
    for (int c0 = 0; c0 < NC; c0 += 32) {
        {
            int cc = t >> 3, nn = (t & 7) * 8;
            const float* src = xb + (size_t)(c0 + cc) * NN + nn;
            *(float4*)&xs[cc][nn]     = *(const float4*)src;
            *(float4*)&xs[cc][nn + 4] = *(const float4*)(src + 4);
        }
        {
            int o = t >> 2, cs = (t & 3) * 8;
            const float* src = W + (size_t)(o0 + o) * NC + c0 + cs;
            #pragma unroll
            for (int k = 0; k < 8; k++) ws[o][cs + k] = src[k];
        }
        __syncthreads();
        #pragma unroll
        for (int cc = 0; cc < 32; cc++) {
            float4 xv = *(const float4*)&xs[cc][gn * 4];
            #pragma unroll
            for (int r = 0; r < 4; r++) {
                float wv = ws[go * 4 + r][cc];
                acc[r][0] = fmaf(wv, xv.x, acc[r][0]);
                acc[r][1] = fmaf(wv, xv.y, acc[r][1]);
                acc[r][2] = fmaf(wv, xv.z, acc[r][2]);
                acc[r][3] = fmaf(wv, xv.w, acc[r][3]);
            }
        }
        __syncthreads();
    }

    float bs[4];
    #pragma unroll
    for (int r = 0; r < 4; r++) bs[r] = bias[o0 + go * 4 + r];
    #pragma unroll
    for (int i = 0; i < 4; i++) {
        int n = n0 + gn * 4 + i;
        unsigned short h[4];
        #pragma unroll
        for (int r = 0; r < 4; r++) h[r] = bfh(acc[r][i] + bs[r]);
        size_t base = ((size_t)(b * NN + n)) * 256 + o0 + go * 4;
        *(ushort4*)&vh[base] = make_ushort4(h[0], h[1], h[2], h[3]);
    }
}

// =====================================================================
extern "C" void kernel_launch(void* const* d_in, const int* in_sizes, int n_in,
                              void* d_out, int out_size)
{
    const float* x  = (const float*)d_in[0];
    const float* Wq = (const float*)d_in[1];
    const float* bq = (const float*)d_in[2];
    const float* Wk = (const float*)d_in[3];
    const float* bk = (const float*)d_in[4];
    const float* Wv = (const float*)d_in[5];
    const float* bv = (const float*)d_in[6];
    float* out = (float*)d_out;

    unsigned short *pq, *pk, *pvh;
    cudaGetSymbolAddress((void**)&pq,  g_q);
    cudaGetSymbolAddress((void**)&pk,  g_k);
    cudaGetSymbolAddress((void**)&pvh, g_vh);

    cudaFuncSetAttribute(attn_kernel, cudaFuncAttributeMaxDynamicSharedMemorySize, SMEMB);

    dim3 blk(256);
    proj_qk2<<<dim3(NN / 64, 1, NB), blk>>>(x, Wq, bq, Wk, bk, pq, pk);
    proj_v<<<dim3(NN / 64, NC / 64, NB), blk>>>(x, Wv, bv, pvh);
    attn_kernel<<<dim3(NN / TI, NB), blk, SMEMB>>>(x, out);
}

// round 6
// speedup vs baseline: 1.7570x; 1.2103x over previous
#include <cuda_runtime.h>
#include <cuda_fp16.h>
#include <cstdint>

#define NB 4
#define NC 256
#define NN 4096
#define TI 128
#define TJ 64
#define NSTEPS (NN / TJ)

// ---------------- device scratch (allocation-free) ----------------
__device__ unsigned short g_q[(size_t)NB * NN * 64];     // [b][n][32hi|32lo] fp16
__device__ unsigned short g_k[(size_t)NB * NN * 64];
__device__ unsigned short g_v[(size_t)NB * NN * 256];    // [b][n][c] fp16

// ---------------- SMEM layout (bytes) ----------------
#define SQ 0                       // 128 rows x 128B = 16384
#define SK 16384                   // + bf*8192 (64 rows x 128B)
#define SV 32768                   // + bf*32768 ; 64 j-rows x 512B
#define SMEMB (32768 + 2 * 32768)  // 98304

// ---------------- PTX helpers ----------------
__device__ __forceinline__ uint32_t smem_u32(const void* p) {
    uint32_t a;
    asm("{ .reg .u64 t; cvta.to.shared.u64 t, %1; cvt.u32.u64 %0, t; }" : "=r"(a) : "l"(p));
    return a;
}
__device__ __forceinline__ void cp16(uint32_t dst, const void* src) {
    asm volatile("cp.async.cg.shared.global [%0], [%1], 16;" :: "r"(dst), "l"(src));
}
__device__ __forceinline__ void cp_commit() { asm volatile("cp.async.commit_group;" ::: "memory"); }
__device__ __forceinline__ void cp_wait0()  { asm volatile("cp.async.wait_group 0;" ::: "memory"); }

__device__ __forceinline__ void ldsm4(uint32_t* r, uint32_t a) {
    asm volatile("ldmatrix.sync.aligned.m8n8.x4.shared.b16 {%0,%1,%2,%3}, [%4];"
        : "=r"(r[0]), "=r"(r[1]), "=r"(r[2]), "=r"(r[3]) : "r"(a));
}
__device__ __forceinline__ void ldsm4t(uint32_t* r, uint32_t a) {
    asm volatile("ldmatrix.sync.aligned.m8n8.x4.trans.shared.b16 {%0,%1,%2,%3}, [%4];"
        : "=r"(r[0]), "=r"(r[1]), "=r"(r[2]), "=r"(r[3]) : "r"(a));
}
__device__ __forceinline__ void mma16816(float* d, const uint32_t* a, uint32_t b0, uint32_t b1) {
    asm volatile("mma.sync.aligned.m16n8k16.row.col.f32.f16.f16.f32 "
        "{%0,%1,%2,%3}, {%4,%5,%6,%7}, {%8,%9}, {%0,%1,%2,%3};"
        : "+f"(d[0]), "+f"(d[1]), "+f"(d[2]), "+f"(d[3])
        : "r"(a[0]), "r"(a[1]), "r"(a[2]), "r"(a[3]), "r"(b0), "r"(b1));
}
// pack: first arg -> low half, second -> high half
__device__ __forceinline__ uint32_t packh(float lo, float hi) {
    uint32_t r;
    asm("cvt.rn.f16x2.f32 %0, %1, %2;" : "=r"(r) : "f"(hi), "f"(lo));
    return r;
}
__device__ __forceinline__ unsigned short f16h(float v) {
    __half h = __float2half_rn(v);
    return *reinterpret_cast<unsigned short*>(&h);
}
__device__ __forceinline__ float f16f(unsigned short u) {
    __half h = *reinterpret_cast<__half*>(&u);
    return __half2float(h);
}

// ---------------- prefetchers (256 threads) ----------------
// phase 1: K hi-plane only (chunks 0-3 of each 128B row)
__device__ __forceinline__ void prefetch_k_hi(uint32_t sb, int bf, int b, int j0, int t) {
    int row = t >> 2, ch = t & 3;
    cp16(sb + SK + bf * 8192 + row * 128 + ((ch ^ (row & 7)) << 4),
         g_k + ((size_t)(b * NN + j0 + row)) * 64 + ch * 8);
}
// phase 2: full K (hi+lo) + V
__device__ __forceinline__ void prefetch_kv(uint32_t sb, int bf, int b, int j0, int t) {
    const unsigned short* ks = g_k + ((size_t)(b * NN + j0)) * 64;
    #pragma unroll
    for (int kk = 0; kk < 2; kk++) {
        int idx = t + kk * 256;
        int row = idx >> 3, ch = idx & 7;
        cp16(sb + SK + bf * 8192 + row * 128 + ((ch ^ (row & 7)) << 4),
             ks + (size_t)row * 64 + ch * 8);
    }
    const unsigned short* hs = g_v + ((size_t)(b * NN + j0)) * 256;
    #pragma unroll
    for (int kk = 0; kk < 8; kk++) {
        int idx = t + kk * 256;
        int row = idx >> 5, ch = idx & 31;
        uint32_t off = row * 512 + (((ch & 24) | ((ch ^ row) & 7)) << 4);
        cp16(sb + SV + bf * 32768 + off, hs + (size_t)row * 256 + ch * 8);
    }
}

// =====================================================================
// fp16 mma.sync flash attention with exact row-max pre-pass.
// Phase 1: QK single hi-product -> row max m (registers only).
// Phase 2: QK 3-product (hi/lo), p = exp(s - m) in fp16, O += P @ V.
// =====================================================================
__global__ __launch_bounds__(256, 1) void attn_kernel(
    const float* __restrict__ x, float* __restrict__ out)
{
    extern __shared__ char smem[];
    const uint32_t sb = smem_u32(smem);
    const int t = threadIdx.x, lane = t & 31, w = t >> 5;
    const int b = blockIdx.y, i0 = blockIdx.x * TI;
    const int rr = lane >> 2, qd = lane & 3;
    const int l7 = lane & 7, lm8 = ((lane >> 3) & 1) * 8, lhi = lane >> 4, lm4 = lane >> 3;

    // ---- prefetch Q tile + first K-hi tile ----
    {
        const unsigned short* qs = g_q + ((size_t)(b * NN + i0)) * 64;
        #pragma unroll
        for (int kk = 0; kk < 4; kk++) {
            int idx = t + kk * 256;
            int row = idx >> 3, ch = idx & 7;
            cp16(sb + SQ + row * 128 + ((ch ^ (row & 7)) << 4),
                 qs + (size_t)row * 64 + ch * 8);
        }
        prefetch_k_hi(sb, 0, b, 0, t);
        cp_commit();
    }
    cp_wait0();
    __syncthreads();

    // ---- resident Q fragments (hi/lo, 2 k-chunks) ----
    uint32_t qh[2][4], ql[2][4];
    #pragma unroll
    for (int kc = 0; kc < 2; kc++) {
        int row = w * 16 + l7 + lm8;
        int chh = 2 * kc + lhi;
        ldsm4(qh[kc], sb + SQ + row * 128 + ((chh ^ (row & 7)) << 4));
        ldsm4(ql[kc], sb + SQ + row * 128 + (((chh + 4) ^ (row & 7)) << 4));
    }

    // ================= PHASE 1: row max =================
    float mx0 = -1e30f, mx1 = -1e30f;
    for (int st = 0; st < NSTEPS; st++) {
        const int bf = st & 1;
        if (st > 0) { cp_wait0(); __syncthreads(); }
        if (st + 1 < NSTEPS) { prefetch_k_hi(sb, bf ^ 1, b, (st + 1) * TJ, t); cp_commit(); }
        const uint32_t kbase = sb + SK + bf * 8192;
        #pragma unroll
        for (int h = 0; h < 8; h++) {
            float S[4] = {0.f, 0.f, 0.f, 0.f};
            int krow = h * 8 + l7;
            int swk = krow & 7;
            uint32_t kh4[4];
            ldsm4(kh4, kbase + krow * 128 + ((lm4 ^ swk) << 4));
            mma16816(S, qh[0], kh4[0], kh4[1]);
            mma16816(S, qh[1], kh4[2], kh4[3]);
            mx0 = fmaxf(mx0, fmaxf(S[0], S[1]));
            mx1 = fmaxf(mx1, fmaxf(S[2], S[3]));
        }
    }
    mx0 = fmaxf(mx0, __shfl_xor_sync(0xffffffffu, mx0, 1));
    mx0 = fmaxf(mx0, __shfl_xor_sync(0xffffffffu, mx0, 2));
    mx1 = fmaxf(mx1, __shfl_xor_sync(0xffffffffu, mx1, 1));
    mx1 = fmaxf(mx1, __shfl_xor_sync(0xffffffffu, mx1, 2));

    // ================= PHASE 2: attention =================
    float O[32][4];
    #pragma unroll
    for (int i = 0; i < 32; i++)
        #pragma unroll
        for (int j = 0; j < 4; j++) O[i][j] = 0.f;
    float rs0 = 0.f, rs1 = 0.f;

    prefetch_kv(sb, 0, b, 0, t);
    cp_commit();
    cp_wait0();
    __syncthreads();

    for (int st = 0; st < NSTEPS; st++) {
        const int bf = st & 1;
        if (st > 0) { cp_wait0(); __syncthreads(); }
        if (st + 1 < NSTEPS) { prefetch_kv(sb, bf ^ 1, b, (st + 1) * TJ, t); cp_commit(); }

        const uint32_t kbase = sb + SK + bf * 8192;
        const uint32_t vbase = sb + SV + bf * 32768;

        #pragma unroll
        for (int kc = 0; kc < 4; kc++) {
            // ---- S for j-blocks 2kc, 2kc+1 (3-product hi/lo) ----
            float S[2][4];
            #pragma unroll
            for (int h = 0; h < 2; h++) {
                S[h][0] = S[h][1] = S[h][2] = S[h][3] = 0.f;
                int krow = (2 * kc + h) * 8 + l7;
                int swk = (krow & 7);
                uint32_t kh4[4], kl4[4];
                ldsm4(kh4, kbase + krow * 128 + ((lm4 ^ swk) << 4));
                ldsm4(kl4, kbase + krow * 128 + (((lm4 + 4) ^ swk) << 4));
                mma16816(S[h], qh[0], kh4[0], kh4[1]);
                mma16816(S[h], qh[1], kh4[2], kh4[3]);
                mma16816(S[h], qh[0], kl4[0], kl4[1]);
                mma16816(S[h], qh[1], kl4[2], kl4[3]);
                mma16816(S[h], ql[0], kh4[0], kh4[1]);
                mma16816(S[h], ql[1], kh4[2], kh4[3]);
            }

            // ---- p = exp(s - m), fp16 pack ----
            uint32_t pah[4];
            #pragma unroll
            for (int h = 0; h < 2; h++) {
                float e0 = __expf(S[h][0] - mx0), e1 = __expf(S[h][1] - mx0);
                float e2 = __expf(S[h][2] - mx1), e3 = __expf(S[h][3] - mx1);
                rs0 += e0 + e1;
                rs1 += e2 + e3;
                pah[h * 2]     = packh(e0, e1);
                pah[h * 2 + 1] = packh(e2, e3);
            }

            // ---- O += P @ V (single fp16 product, 32 channel-blocks) ----
            int vrow = kc * 16 + l7 + lm8;
            uint32_t vroff = vbase + vrow * 512;
            int swv = (vrow & 7);
            #pragma unroll
            for (int vb = 0; vb < 16; vb++) {
                int ch = vb * 2 + lhi;
                uint32_t a = vroff + ((((ch & 24) | ((ch ^ swv) & 7))) << 4);
                uint32_t vh4[4];
                ldsm4t(vh4, a);
                mma16816(O[2 * vb],     pah, vh4[0], vh4[1]);
                mma16816(O[2 * vb + 1], pah, vh4[2], vh4[3]);
            }
        }
    }

    // ---- row-sum reduce + epilogue (O/l + residual) ----
    rs0 += __shfl_xor_sync(0xffffffffu, rs0, 1);
    rs0 += __shfl_xor_sync(0xffffffffu, rs0, 2);
    rs1 += __shfl_xor_sync(0xffffffffu, rs1, 1);
    rs1 += __shfl_xor_sync(0xffffffffu, rs1, 2);
    const float li0 = 1.0f / rs0, li1 = 1.0f / rs1;

    const int ng = i0 + w * 16 + rr;
    #pragma unroll
    for (int nb = 0; nb < 32; nb++) {
        int c = nb * 8 + qd * 2;
        size_t g = ((size_t)b * NC + c) * NN + ng;
        out[g]          = O[nb][0] * li0 + x[g];
        out[g + NN]     = O[nb][1] * li0 + x[g + NN];
        out[g + 8]      = O[nb][2] * li1 + x[g + 8];
        out[g + 8 + NN] = O[nb][3] * li1 + x[g + 8 + NN];
    }
}

// =====================================================================
// Fused Q+K projection: reads x once, writes both [b][n][32hi|32lo] fp16
// =====================================================================
__global__ __launch_bounds__(256) void proj_qk2(
    const float* __restrict__ x,
    const float* __restrict__ Wq, const float* __restrict__ bq,
    const float* __restrict__ Wk, const float* __restrict__ bk,
    unsigned short* __restrict__ oq, unsigned short* __restrict__ ok)
{
    __shared__ float xs[32][64];
    __shared__ float wqs[32][33];
    __shared__ float wks[32][33];
    const int b  = blockIdx.z;
    const int n0 = blockIdx.x * 64;
    const int t  = threadIdx.x;
    const int go = t & 7, gn = t >> 3;

    float aq[4][2], ak[4][2];
    #pragma unroll
    for (int r = 0; r < 4; r++) {
        aq[r][0] = aq[r][1] = 0.f;
        ak[r][0] = ak[r][1] = 0.f;
    }

    const float* xb = x + (size_t)b * NC * NN + n0;
    for (int c0 = 0; c0 < NC; c0 += 32) {
        {
            int cc = t >> 3, nn = (t & 7) * 8;
            const float* src = xb + (size_t)(c0 + cc) * NN + nn;
            *(float4*)&xs[cc][nn]     = *(const float4*)src;
            *(float4*)&xs[cc][nn + 4] = *(const float4*)(src + 4);
        }
        {
            int o = t >> 3, c4 = (t & 7) * 4;
            const float* sq = Wq + (size_t)o * NC + c0 + c4;
            const float* sk = Wk + (size_t)o * NC + c0 + c4;
            #pragma unroll
            for (int k = 0; k < 4; k++) { wqs[o][c4 + k] = sq[k]; wks[o][c4 + k] = sk[k]; }
        }
        __syncthreads();
        #pragma unroll
        for (int cc = 0; cc < 32; cc++) {
            float x0 = xs[cc][gn * 2], x1 = xs[cc][gn * 2 + 1];
            #pragma unroll
            for (int r = 0; r < 4; r++) {
                float wv = wqs[go * 4 + r][cc];
                aq[r][0] = fmaf(wv, x0, aq[r][0]);
                aq[r][1] = fmaf(wv, x1, aq[r][1]);
                float wk2 = wks[go * 4 + r][cc];
                ak[r][0] = fmaf(wk2, x0, ak[r][0]);
                ak[r][1] = fmaf(wk2, x1, ak[r][1]);
            }
        }
        __syncthreads();
    }

    float bsq[4], bsk[4];
    #pragma unroll
    for (int r = 0; r < 4; r++) { bsq[r] = bq[go * 4 + r]; bsk[r] = bk[go * 4 + r]; }
    #pragma unroll
    for (int i = 0; i < 2; i++) {
        int n = n0 + gn * 2 + i;
        size_t base = ((size_t)(b * NN + n)) * 64 + go * 4;
        unsigned short h[4], l[4];
        #pragma unroll
        for (int r = 0; r < 4; r++) {
            float v = aq[r][i] + bsq[r];
            h[r] = f16h(v);
            l[r] = f16h(v - f16f(h[r]));
        }
        *(ushort4*)&oq[base]      = make_ushort4(h[0], h[1], h[2], h[3]);
        *(ushort4*)&oq[base + 32] = make_ushort4(l[0], l[1], l[2], l[3]);
        #pragma unroll
        for (int r = 0; r < 4; r++) {
            float v = ak[r][i] + bsk[r];
            h[r] = f16h(v);
            l[r] = f16h(v - f16f(h[r]));
        }
        *(ushort4*)&ok[base]      = make_ushort4(h[0], h[1], h[2], h[3]);
        *(ushort4*)&ok[base + 32] = make_ushort4(l[0], l[1], l[2], l[3]);
    }
}

// =====================================================================
// Projection V: [b][n][256] fp16
// =====================================================================
__global__ __launch_bounds__(256) void proj_v(
    const float* __restrict__ x, const float* __restrict__ W,
    const float* __restrict__ bias, unsigned short* __restrict__ vh)
{
    __shared__ float xs[32][64];
    __shared__ float ws[64][33];
    const int b  = blockIdx.z;
    const int n0 = blockIdx.x * 64;
    const int o0 = blockIdx.y * 64;
    const int t  = threadIdx.x;
    const int gn = t & 15, go = t >> 4;

    float acc[4][4];
    #pragma unroll
    for (int r = 0; r < 4; r++)
        #pragma unroll
        for (int i = 0; i < 4; i++) acc[r][i] = 0.f;

    const float* xb = x + (size_t)b * NC * NN + n0;
    for (int c0 = 0; c0 < NC; c0 += 32) {
        {
            int cc = t >> 3, nn = (t & 7) * 8;
            const float* src = xb + (size_t)(c0 + cc) * NN + nn;
            *(float4*)&xs[cc][nn]     = *(const float4*)src;
            *(float4*)&xs[cc][nn + 4] = *(const float4*)(src + 4);
        }
        {
            int o = t >> 2, cs = (t & 3) * 8;
            const float* src = W + (size_t)(o0 + o) * NC + c0 + cs;
            #pragma unroll
            for (int k = 0; k < 8; k++) ws[o][cs + k] = src[k];
        }
        __syncthreads();
        #pragma unroll
        for (int cc = 0; cc < 32; cc++) {
            float4 xv = *(const float4*)&xs[cc][gn * 4];
            #pragma unroll
            for (int r = 0; r < 4; r++) {
                float wv = ws[go * 4 + r][cc];
                acc[r][0] = fmaf(wv, xv.x, acc[r][0]);
                acc[r][1] = fmaf(wv, xv.y, acc[r][1]);
                acc[r][2] = fmaf(wv, xv.z, acc[r][2]);
                acc[r][3] = fmaf(wv, xv.w, acc[r][3]);
            }
        }
        __syncthreads();
    }

    float bs[4];
    #pragma unroll
    for (int r = 0; r < 4; r++) bs[r] = bias[o0 + go * 4 + r];
    #pragma unroll
    for (int i = 0; i < 4; i++) {
        int n = n0 + gn * 4 + i;
        unsigned short h[4];
        #pragma unroll
        for (int r = 0; r < 4; r++) h[r] = f16h(acc[r][i] + bs[r]);
        size_t base = ((size_t)(b * NN + n)) * 256 + o0 + go * 4;
        *(ushort4*)&vh[base] = make_ushort4(h[0], h[1], h[2], h[3]);
    }
}

// =====================================================================
extern "C" void kernel_launch(void* const* d_in, const int* in_sizes, int n_in,
                              void* d_out, int out_size)
{
    const float* x  = (const float*)d_in[0];
    const float* Wq = (const float*)d_in[1];
    const float* bq = (const float*)d_in[2];
    const float* Wk = (const float*)d_in[3];
    const float* bk = (const float*)d_in[4];
    const float* Wv = (const float*)d_in[5];
    const float* bv = (const float*)d_in[6];
    float* out = (float*)d_out;

    unsigned short *pq, *pk, *pv;
    cudaGetSymbolAddress((void**)&pq, g_q);
    cudaGetSymbolAddress((void**)&pk, g_k);
    cudaGetSymbolAddress((void**)&pv, g_v);

    cudaFuncSetAttribute(attn_kernel, cudaFuncAttributeMaxDynamicSharedMemorySize, SMEMB);

    dim3 blk(256);
    proj_qk2<<<dim3(NN / 64, 1, NB), blk>>>(x, Wq, bq, Wk, bk, pq, pk);
    proj_v<<<dim3(NN / 64, NC / 64, NB), blk>>>(x, Wv, bv, pv);
    attn_kernel<<<dim3(NN / TI, NB), blk, SMEMB>>>(x, out);
}

// round 7
// speedup vs baseline: 1.8110x; 1.0307x over previous
#include <cuda_runtime.h>
#include <cuda_fp16.h>
#include <cstdint>

#define NB 4
#define NC 256
#define NN 4096
#define TI 128
#define TJ 64
#define NSTEPS (NN / TJ)
#define TJ1 256
#define NSTEPS1 (NN / TJ1)

// ---------------- device scratch (allocation-free) ----------------
__device__ unsigned short g_q[(size_t)NB * NN * 64];     // [b][n][32hi|32lo] fp16
__device__ unsigned short g_k[(size_t)NB * NN * 64];
__device__ unsigned short g_v[(size_t)NB * NN * 256];    // [b][n][c] fp16

// ---------------- SMEM layout (bytes) ----------------
#define SQ 0                       // 128 rows x 128B = 16384
#define SK 16384                   // + bf*8192 (64 rows x 128B)
#define SV 32768                   // + bf*32768 ; 64 j-rows x 512B
                                   // (phase 1 reuses SV region: 2 x 16384 K-hi tiles)
#define SMEMB (32768 + 2 * 32768)  // 98304

// ---------------- PTX helpers ----------------
__device__ __forceinline__ uint32_t smem_u32(const void* p) {
    uint32_t a;
    asm("{ .reg .u64 t; cvta.to.shared.u64 t, %1; cvt.u32.u64 %0, t; }" : "=r"(a) : "l"(p));
    return a;
}
__device__ __forceinline__ void cp16(uint32_t dst, const void* src) {
    asm volatile("cp.async.cg.shared.global [%0], [%1], 16;" :: "r"(dst), "l"(src));
}
__device__ __forceinline__ void cp_commit() { asm volatile("cp.async.commit_group;" ::: "memory"); }
__device__ __forceinline__ void cp_wait0()  { asm volatile("cp.async.wait_group 0;" ::: "memory"); }

__device__ __forceinline__ void ldsm4(uint32_t* r, uint32_t a) {
    asm volatile("ldmatrix.sync.aligned.m8n8.x4.shared.b16 {%0,%1,%2,%3}, [%4];"
        : "=r"(r[0]), "=r"(r[1]), "=r"(r[2]), "=r"(r[3]) : "r"(a));
}
__device__ __forceinline__ void ldsm4t(uint32_t* r, uint32_t a) {
    asm volatile("ldmatrix.sync.aligned.m8n8.x4.trans.shared.b16 {%0,%1,%2,%3}, [%4];"
        : "=r"(r[0]), "=r"(r[1]), "=r"(r[2]), "=r"(r[3]) : "r"(a));
}
__device__ __forceinline__ void mma16816(float* d, const uint32_t* a, uint32_t b0, uint32_t b1) {
    asm volatile("mma.sync.aligned.m16n8k16.row.col.f32.f16.f16.f32 "
        "{%0,%1,%2,%3}, {%4,%5,%6,%7}, {%8,%9}, {%0,%1,%2,%3};"
        : "+f"(d[0]), "+f"(d[1]), "+f"(d[2]), "+f"(d[3])
        : "r"(a[0]), "r"(a[1]), "r"(a[2]), "r"(a[3]), "r"(b0), "r"(b1));
}
// pack: first arg -> low half, second -> high half
__device__ __forceinline__ uint32_t packh(float lo, float hi) {
    uint32_t r;
    asm("cvt.rn.f16x2.f32 %0, %1, %2;" : "=r"(r) : "f"(hi), "f"(lo));
    return r;
}
__device__ __forceinline__ unsigned short f16h(float v) {
    __half h = __float2half_rn(v);
    return *reinterpret_cast<unsigned short*>(&h);
}
__device__ __forceinline__ float f16f(unsigned short u) {
    __half h = *reinterpret_cast<__half*>(&u);
    return __half2float(h);
}
// ---- packed fp32x2 (FFMA2) ----
__device__ __forceinline__ unsigned long long pack2(float x, float y) {
    unsigned long long r;
    asm("mov.b64 %0, {%1, %2};" : "=l"(r) : "f"(x), "f"(y));
    return r;
}
__device__ __forceinline__ void fma2(unsigned long long& a, unsigned long long b, unsigned long long c) {
    asm("fma.rn.f32x2 %0, %1, %2, %0;" : "+l"(a) : "l"(b), "l"(c));
}
__device__ __forceinline__ float2 unpack2(unsigned long long v) {
    float x, y;
    asm("mov.b64 {%0, %1}, %2;" : "=f"(x), "=f"(y) : "l"(v));
    return make_float2(x, y);
}

// ---------------- prefetchers (256 threads) ----------------
// phase 1: K hi-plane, 256 rows x 64B, swizzled for 64B-row ldsm
__device__ __forceinline__ void prefetch_k256(uint32_t sb, int bf, int b, int j0, int t) {
    #pragma unroll
    for (int kk = 0; kk < 4; kk++) {
        int idx = t + kk * 256;
        int row = idx >> 2, ch = idx & 3;
        cp16(sb + SV + bf * 16384 + row * 64 + ((ch ^ ((row >> 1) & 3)) << 4),
             g_k + ((size_t)(b * NN + j0 + row)) * 64 + ch * 8);
    }
}
// phase 2: full K (hi+lo) + V
__device__ __forceinline__ void prefetch_kv(uint32_t sb, int bf, int b, int j0, int t) {
    const unsigned short* ks = g_k + ((size_t)(b * NN + j0)) * 64;
    #pragma unroll
    for (int kk = 0; kk < 2; kk++) {
        int idx = t + kk * 256;
        int row = idx >> 3, ch = idx & 7;
        cp16(sb + SK + bf * 8192 + row * 128 + ((ch ^ (row & 7)) << 4),
             ks + (size_t)row * 64 + ch * 8);
    }
    const unsigned short* hs = g_v + ((size_t)(b * NN + j0)) * 256;
    #pragma unroll
    for (int kk = 0; kk < 8; kk++) {
        int idx = t + kk * 256;
        int row = idx >> 5, ch = idx & 31;
        uint32_t off = row * 512 + (((ch & 24) | ((ch ^ row) & 7)) << 4);
        cp16(sb + SV + bf * 32768 + off, hs + (size_t)row * 256 + ch * 8);
    }
}

// =====================================================================
// fp16 mma.sync flash attention with exact row-max pre-pass.
// Phase 1 (TJ1=256 tiles): QK hi-product -> row max m (registers only).
// Phase 2: QK 3-product (hi/lo), p = exp(s - m) in fp16, O += P @ V.
// =====================================================================
__global__ __launch_bounds__(256, 1) void attn_kernel(
    const float* __restrict__ x, float* __restrict__ out)
{
    extern __shared__ char smem[];
    const uint32_t sb = smem_u32(smem);
    const int t = threadIdx.x, lane = t & 31, w = t >> 5;
    const int b = blockIdx.y, i0 = blockIdx.x * TI;
    const int rr = lane >> 2, qd = lane & 3;
    const int l7 = lane & 7, lm8 = ((lane >> 3) & 1) * 8, lhi = lane >> 4, lm4 = lane >> 3;

    // ---- prefetch Q tile + first phase-1 K tile ----
    {
        const unsigned short* qs = g_q + ((size_t)(b * NN + i0)) * 64;
        #pragma unroll
        for (int kk = 0; kk < 4; kk++) {
            int idx = t + kk * 256;
            int row = idx >> 3, ch = idx & 7;
            cp16(sb + SQ + row * 128 + ((ch ^ (row & 7)) << 4),
                 qs + (size_t)row * 64 + ch * 8);
        }
        prefetch_k256(sb, 0, b, 0, t);
        cp_commit();
    }
    cp_wait0();
    __syncthreads();

    // ---- resident Q fragments (hi/lo, 2 k-chunks) ----
    uint32_t qh[2][4], ql[2][4];
    #pragma unroll
    for (int kc = 0; kc < 2; kc++) {
        int row = w * 16 + l7 + lm8;
        int chh = 2 * kc + lhi;
        ldsm4(qh[kc], sb + SQ + row * 128 + ((chh ^ (row & 7)) << 4));
        ldsm4(ql[kc], sb + SQ + row * 128 + (((chh + 4) ^ (row & 7)) << 4));
    }

    // ================= PHASE 1: row max (16 big tiles) =================
    float mx0 = -1e30f, mx1 = -1e30f;
    for (int it = 0; it < NSTEPS1; it++) {
        const int bf = it & 1;
        if (it > 0) { cp_wait0(); __syncthreads(); }
        if (it + 1 < NSTEPS1) { prefetch_k256(sb, bf ^ 1, b, (it + 1) * TJ1, t); cp_commit(); }
        const uint32_t kb = sb + SV + bf * 16384;
        #pragma unroll
        for (int hb = 0; hb < 32; hb++) {
            float S[4] = {0.f, 0.f, 0.f, 0.f};
            int krow = hb * 8 + l7;
            uint32_t a = kb + krow * 64 + ((lm4 ^ ((krow >> 1) & 3)) << 4);
            uint32_t kh4[4];
            ldsm4(kh4, a);
            mma16816(S, qh[0], kh4[0], kh4[1]);
            mma16816(S, qh[1], kh4[2], kh4[3]);
            mx0 = fmaxf(mx0, fmaxf(S[0], S[1]));
            mx1 = fmaxf(mx1, fmaxf(S[2], S[3]));
        }
    }
    mx0 = fmaxf(mx0, __shfl_xor_sync(0xffffffffu, mx0, 1));
    mx0 = fmaxf(mx0, __shfl_xor_sync(0xffffffffu, mx0, 2));
    mx1 = fmaxf(mx1, __shfl_xor_sync(0xffffffffu, mx1, 1));
    mx1 = fmaxf(mx1, __shfl_xor_sync(0xffffffffu, mx1, 2));

    // ================= PHASE 2: attention =================
    float O[32][4];
    #pragma unroll
    for (int i = 0; i < 32; i++)
        #pragma unroll
        for (int j = 0; j < 4; j++) O[i][j] = 0.f;
    float rs0 = 0.f, rs1 = 0.f;

    __syncthreads();          // all phase-1 reads of SV region done
    prefetch_kv(sb, 0, b, 0, t);
    cp_commit();
    cp_wait0();
    __syncthreads();

    for (int st = 0; st < NSTEPS; st++) {
        const int bf = st & 1;
        if (st > 0) { cp_wait0(); __syncthreads(); }
        if (st + 1 < NSTEPS) { prefetch_kv(sb, bf ^ 1, b, (st + 1) * TJ, t); cp_commit(); }

        const uint32_t kbase = sb + SK + bf * 8192;
        const uint32_t vbase = sb + SV + bf * 32768;

        #pragma unroll
        for (int kc = 0; kc < 4; kc++) {
            // ---- S for j-blocks 2kc, 2kc+1 (3-product hi/lo) ----
            float S[2][4];
            #pragma unroll
            for (int h = 0; h < 2; h++) {
                S[h][0] = S[h][1] = S[h][2] = S[h][3] = 0.f;
                int krow = (2 * kc + h) * 8 + l7;
                int swk = (krow & 7);
                uint32_t kh4[4], kl4[4];
                ldsm4(kh4, kbase + krow * 128 + ((lm4 ^ swk) << 4));
                ldsm4(kl4, kbase + krow * 128 + (((lm4 + 4) ^ swk) << 4));
                mma16816(S[h], qh[0], kh4[0], kh4[1]);
                mma16816(S[h], qh[1], kh4[2], kh4[3]);
                mma16816(S[h], qh[0], kl4[0], kl4[1]);
                mma16816(S[h], qh[1], kl4[2], kl4[3]);
                mma16816(S[h], ql[0], kh4[0], kh4[1]);
                mma16816(S[h], ql[1], kh4[2], kh4[3]);
            }

            // ---- p = exp(s - m), fp16 pack ----
            uint32_t pah[4];
            #pragma unroll
            for (int h = 0; h < 2; h++) {
                float e0 = __expf(S[h][0] - mx0), e1 = __expf(S[h][1] - mx0);
                float e2 = __expf(S[h][2] - mx1), e3 = __expf(S[h][3] - mx1);
                rs0 += e0 + e1;
                rs1 += e2 + e3;
                pah[h * 2]     = packh(e0, e1);
                pah[h * 2 + 1] = packh(e2, e3);
            }

            // ---- O += P @ V (single fp16 product, 32 channel-blocks) ----
            int vrow = kc * 16 + l7 + lm8;
            uint32_t vroff = vbase + vrow * 512;
            int swv = (vrow & 7);
            #pragma unroll
            for (int vb = 0; vb < 16; vb++) {
                int ch = vb * 2 + lhi;
                uint32_t a = vroff + ((((ch & 24) | ((ch ^ swv) & 7))) << 4);
                uint32_t vh4[4];
                ldsm4t(vh4, a);
                mma16816(O[2 * vb],     pah, vh4[0], vh4[1]);
                mma16816(O[2 * vb + 1], pah, vh4[2], vh4[3]);
            }
        }
    }

    // ---- row-sum reduce + epilogue (O/l + residual) ----
    rs0 += __shfl_xor_sync(0xffffffffu, rs0, 1);
    rs0 += __shfl_xor_sync(0xffffffffu, rs0, 2);
    rs1 += __shfl_xor_sync(0xffffffffu, rs1, 1);
    rs1 += __shfl_xor_sync(0xffffffffu, rs1, 2);
    const float li0 = 1.0f / rs0, li1 = 1.0f / rs1;

    const int ng = i0 + w * 16 + rr;
    #pragma unroll
    for (int nb = 0; nb < 32; nb++) {
        int c = nb * 8 + qd * 2;
        size_t g = ((size_t)b * NC + c) * NN + ng;
        out[g]          = O[nb][0] * li0 + x[g];
        out[g + NN]     = O[nb][1] * li0 + x[g + NN];
        out[g + 8]      = O[nb][2] * li1 + x[g + 8];
        out[g + 8 + NN] = O[nb][3] * li1 + x[g + 8 + NN];
    }
}

// =====================================================================
// Fused Q+K projection (packed f32x2): [b][n][32hi|32lo] fp16
// Weight tiles stored transposed [cc][o] so w-pairs load via LDS.64.
// =====================================================================
__global__ __launch_bounds__(256) void proj_qk2(
    const float* __restrict__ x,
    const float* __restrict__ Wq, const float* __restrict__ bq,
    const float* __restrict__ Wk, const float* __restrict__ bk,
    unsigned short* __restrict__ oq, unsigned short* __restrict__ ok)
{
    __shared__ float xs[32][64];
    __shared__ float wqs[32][34];   // [cc][o], 34 keeps rows 8B-aligned
    __shared__ float wks[32][34];
    const int b  = blockIdx.z;
    const int n0 = blockIdx.x * 64;
    const int t  = threadIdx.x;
    const int go = t & 7, gn = t >> 3;

    // acc pairs over (r, r+1): [rpair][i], low half = even r
    unsigned long long aq[2][2], ak[2][2];
    #pragma unroll
    for (int rp = 0; rp < 2; rp++) {
        aq[rp][0] = aq[rp][1] = 0ull;
        ak[rp][0] = ak[rp][1] = 0ull;
    }

    const float* xb = x + (size_t)b * NC * NN + n0;
    for (int c0 = 0; c0 < NC; c0 += 32) {
        {
            int cc = t >> 3, nn = (t & 7) * 8;
            const float* src = xb + (size_t)(c0 + cc) * NN + nn;
            *(float4*)&xs[cc][nn]     = *(const float4*)src;
            *(float4*)&xs[cc][nn + 4] = *(const float4*)(src + 4);
        }
        {
            int o = t >> 3, c4 = (t & 7) * 4;
            const float* sq = Wq + (size_t)o * NC + c0 + c4;
            const float* sk = Wk + (size_t)o * NC + c0 + c4;
            #pragma unroll
            for (int k = 0; k < 4; k++) { wqs[c4 + k][o] = sq[k]; wks[c4 + k][o] = sk[k]; }
        }
        __syncthreads();
        #pragma unroll
        for (int cc = 0; cc < 32; cc++) {
            float x0 = xs[cc][gn * 2], x1 = xs[cc][gn * 2 + 1];
            unsigned long long xx0 = pack2(x0, x0), xx1 = pack2(x1, x1);
            #pragma unroll
            for (int rp = 0; rp < 2; rp++) {
                unsigned long long wq2 = *(const unsigned long long*)&wqs[cc][go * 4 + rp * 2];
                fma2(aq[rp][0], wq2, xx0);
                fma2(aq[rp][1], wq2, xx1);
                unsigned long long wk2 = *(const unsigned long long*)&wks[cc][go * 4 + rp * 2];
                fma2(ak[rp][0], wk2, xx0);
                fma2(ak[rp][1], wk2, xx1);
            }
        }
        __syncthreads();
    }

    float bsq[4], bsk[4];
    #pragma unroll
    for (int r = 0; r < 4; r++) { bsq[r] = bq[go * 4 + r]; bsk[r] = bk[go * 4 + r]; }
    #pragma unroll
    for (int i = 0; i < 2; i++) {
        int n = n0 + gn * 2 + i;
        size_t base = ((size_t)(b * NN + n)) * 64 + go * 4;
        unsigned short h[4], l[4];
        #pragma unroll
        for (int rp = 0; rp < 2; rp++) {
            float2 f = unpack2(aq[rp][i]);
            float v0 = f.x + bsq[rp * 2], v1 = f.y + bsq[rp * 2 + 1];
            h[rp * 2] = f16h(v0);     l[rp * 2] = f16h(v0 - f16f(h[rp * 2]));
            h[rp * 2 + 1] = f16h(v1); l[rp * 2 + 1] = f16h(v1 - f16f(h[rp * 2 + 1]));
        }
        *(ushort4*)&oq[base]      = make_ushort4(h[0], h[1], h[2], h[3]);
        *(ushort4*)&oq[base + 32] = make_ushort4(l[0], l[1], l[2], l[3]);
        #pragma unroll
        for (int rp = 0; rp < 2; rp++) {
            float2 f = unpack2(ak[rp][i]);
            float v0 = f.x + bsk[rp * 2], v1 = f.y + bsk[rp * 2 + 1];
            h[rp * 2] = f16h(v0);     l[rp * 2] = f16h(v0 - f16f(h[rp * 2]));
            h[rp * 2 + 1] = f16h(v1); l[rp * 2 + 1] = f16h(v1 - f16f(h[rp * 2 + 1]));
        }
        *(ushort4*)&ok[base]      = make_ushort4(h[0], h[1], h[2], h[3]);
        *(ushort4*)&ok[base + 32] = make_ushort4(l[0], l[1], l[2], l[3]);
    }
}

// =====================================================================
// Projection V (packed f32x2): [b][n][256] fp16
// =====================================================================
__global__ __launch_bounds__(256) void proj_v(
    const float* __restrict__ x, const float* __restrict__ W,
    const float* __restrict__ bias, unsigned short* __restrict__ vh)
{
    __shared__ float xs[32][64];
    __shared__ float ws[32][66];    // [cc][o], 66 keeps rows 8B-aligned
    const int b  = blockIdx.z;
    const int n0 = blockIdx.x * 64;
    const int o0 = blockIdx.y * 64;
    const int t  = threadIdx.x;
    const int gn = t & 15, go = t >> 4;

    // acc pairs over (r, r+1): [rpair][i 4]
    unsigned long long acc[2][4];
    #pragma unroll
    for (int rp = 0; rp < 2; rp++)
        #pragma unroll
        for (int i = 0; i < 4; i++) acc[rp][i] = 0ull;

    const float* xb = x + (size_t)b * NC * NN + n0;
    for (int c0 = 0; c0 < NC; c0 += 32) {
        {
            int cc = t >> 3, nn = (t & 7) * 8;
            const float* src = xb + (size_t)(c0 + cc) * NN + nn;
            *(float4*)&xs[cc][nn]     = *(const float4*)src;
            *(float4*)&xs[cc][nn + 4] = *(const float4*)(src + 4);
        }
        {
            int o = t >> 2, cs = (t & 3) * 8;
            const float* src = W + (size_t)(o0 + o) * NC + c0 + cs;
            #pragma unroll
            for (int k = 0; k < 8; k++) ws[cs + k][o] = src[k];
        }
        __syncthreads();
        #pragma unroll
        for (int cc = 0; cc < 32; cc++) {
            float4 xv = *(const float4*)&xs[cc][gn * 4];
            unsigned long long xx[4];
            xx[0] = pack2(xv.x, xv.x); xx[1] = pack2(xv.y, xv.y);
            xx[2] = pack2(xv.z, xv.z); xx[3] = pack2(xv.w, xv.w);
            #pragma unroll
            for (int rp = 0; rp < 2; rp++) {
                unsigned long long w2 = *(const unsigned long long*)&ws[cc][go * 4 + rp * 2];
                fma2(acc[rp][0], w2, xx[0]);
                fma2(acc[rp][1], w2, xx[1]);
                fma2(acc[rp][2], w2, xx[2]);
                fma2(acc[rp][3], w2, xx[3]);
            }
        }
        __syncthreads();
    }

    float bs[4];
    #pragma unroll
    for (int r = 0; r < 4; r++) bs[r] = bias[o0 + go * 4 + r];
    #pragma unroll
    for (int i = 0; i < 4; i++) {
        int n = n0 + gn * 4 + i;
        unsigned short h[4];
        #pragma unroll
        for (int rp = 0; rp < 2; rp++) {
            float2 f = unpack2(acc[rp][i]);
            h[rp * 2]     = f16h(f.x + bs[rp * 2]);
            h[rp * 2 + 1] = f16h(f.y + bs[rp * 2 + 1]);
        }
        size_t base = ((size_t)(b * NN + n)) * 256 + o0 + go * 4;
        *(ushort4*)&vh[base] = make_ushort4(h[0], h[1], h[2], h[3]);
    }
}

// =====================================================================
extern "C" void kernel_launch(void* const* d_in, const int* in_sizes, int n_in,
                              void* d_out, int out_size)
{
    const float* x  = (const float*)d_in[0];
    const float* Wq = (const float*)d_in[1];
    const float* bq = (const float*)d_in[2];
    const float* Wk = (const float*)d_in[3];
    const float* bk = (const float*)d_in[4];
    const float* Wv = (const float*)d_in[5];
    const float* bv = (const float*)d_in[6];
    float* out = (float*)d_out;

    unsigned short *pq, *pk, *pv;
    cudaGetSymbolAddress((void**)&pq, g_q);
    cudaGetSymbolAddress((void**)&pk, g_k);
    cudaGetSymbolAddress((void**)&pv, g_v);

    cudaFuncSetAttribute(attn_kernel, cudaFuncAttributeMaxDynamicSharedMemorySize, SMEMB);

    dim3 blk(256);
    proj_qk2<<<dim3(NN / 64, 1, NB), blk>>>(x, Wq, bq, Wk, bk, pq, pk);
    proj_v<<<dim3(NN / 64, NC / 64, NB), blk>>>(x, Wv, bv, pv);
    attn_kernel<<<dim3(NN / TI, NB), blk, SMEMB>>>(x, out);
}

// round 8
// speedup vs baseline: 1.8466x; 1.0197x over previous
#include <cuda_runtime.h>
#include <cuda_fp16.h>
#include <cstdint>

#define NB 4
#define NC 256
#define NN 4096
#define TI 64
#define TJ 64
#define NSTEPS (NN / TJ)
#define TJ1 256
#define NSTEPS1 (NN / TJ1)

// ---------------- device scratch (allocation-free) ----------------
__device__ unsigned short g_q[(size_t)NB * NN * 64];     // [b][n][32hi|32lo] fp16
__device__ unsigned short g_k[(size_t)NB * NN * 64];
__device__ unsigned short g_v[(size_t)NB * NN * 256];    // [b][n][c] fp16

// ---------------- attn SMEM layout (bytes) ----------------
#define SQ 0                       // 64 rows x 128B = 8192
#define SK 8192                    // + bf*8192 (64 rows x 128B), 2 bufs
#define SV 24576                   // + bf*32768 ; 64 j-rows x 512B, 2 bufs
                                   // (phase 1 reuses SV region: 2 x 16384 K-hi tiles)
#define SMEMB (24576 + 2 * 32768)  // 90112 -> 2 CTAs/SM

// ---------------- PTX helpers ----------------
__device__ __forceinline__ uint32_t smem_u32(const void* p) {
    uint32_t a;
    asm("{ .reg .u64 t; cvta.to.shared.u64 t, %1; cvt.u32.u64 %0, t; }" : "=r"(a) : "l"(p));
    return a;
}
__device__ __forceinline__ void cp16(uint32_t dst, const void* src) {
    asm volatile("cp.async.cg.shared.global [%0], [%1], 16;" :: "r"(dst), "l"(src));
}
__device__ __forceinline__ void cp_commit() { asm volatile("cp.async.commit_group;" ::: "memory"); }
__device__ __forceinline__ void cp_wait0()  { asm volatile("cp.async.wait_group 0;" ::: "memory"); }

__device__ __forceinline__ void ldsm4(uint32_t* r, uint32_t a) {
    asm volatile("ldmatrix.sync.aligned.m8n8.x4.shared.b16 {%0,%1,%2,%3}, [%4];"
        : "=r"(r[0]), "=r"(r[1]), "=r"(r[2]), "=r"(r[3]) : "r"(a));
}
__device__ __forceinline__ void ldsm4t(uint32_t* r, uint32_t a) {
    asm volatile("ldmatrix.sync.aligned.m8n8.x4.trans.shared.b16 {%0,%1,%2,%3}, [%4];"
        : "=r"(r[0]), "=r"(r[1]), "=r"(r[2]), "=r"(r[3]) : "r"(a));
}
__device__ __forceinline__ void mma16816(float* d, const uint32_t* a, uint32_t b0, uint32_t b1) {
    asm volatile("mma.sync.aligned.m16n8k16.row.col.f32.f16.f16.f32 "
        "{%0,%1,%2,%3}, {%4,%5,%6,%7}, {%8,%9}, {%0,%1,%2,%3};"
        : "+f"(d[0]), "+f"(d[1]), "+f"(d[2]), "+f"(d[3])
        : "r"(a[0]), "r"(a[1]), "r"(a[2]), "r"(a[3]), "r"(b0), "r"(b1));
}
// pack: first arg -> low half, second -> high half
__device__ __forceinline__ uint32_t packh(float lo, float hi) {
    uint32_t r;
    asm("cvt.rn.f16x2.f32 %0, %1, %2;" : "=r"(r) : "f"(hi), "f"(lo));
    return r;
}
__device__ __forceinline__ unsigned short f16h(float v) {
    __half h = __float2half_rn(v);
    return *reinterpret_cast<unsigned short*>(&h);
}
__device__ __forceinline__ float f16f(unsigned short u) {
    __half h = *reinterpret_cast<__half*>(&u);
    return __half2float(h);
}
// ---- packed fp32x2 (FFMA2) ----
__device__ __forceinline__ unsigned long long pack2(float x, float y) {
    unsigned long long r;
    asm("mov.b64 %0, {%1, %2};" : "=l"(r) : "f"(x), "f"(y));
    return r;
}
__device__ __forceinline__ void fma2(unsigned long long& a, unsigned long long b, unsigned long long c) {
    asm("fma.rn.f32x2 %0, %1, %2, %0;" : "+l"(a) : "l"(b), "l"(c));
}
__device__ __forceinline__ float2 unpack2(unsigned long long v) {
    float x, y;
    asm("mov.b64 {%0, %1}, %2;" : "=f"(x), "=f"(y) : "l"(v));
    return make_float2(x, y);
}

// ---------------- attn prefetchers (128 threads) ----------------
// phase 1: K hi-plane, 256 rows x 64B, swizzled for 64B-row ldsm
__device__ __forceinline__ void prefetch_k256(uint32_t sb, int bf, int b, int j0, int t) {
    #pragma unroll
    for (int kk = 0; kk < 8; kk++) {
        int idx = t + kk * 128;
        int row = idx >> 2, ch = idx & 3;
        cp16(sb + SV + bf * 16384 + row * 64 + ((ch ^ ((row >> 1) & 3)) << 4),
             g_k + ((size_t)(b * NN + j0 + row)) * 64 + ch * 8);
    }
}
// phase 2: full K (hi+lo) + V
__device__ __forceinline__ void prefetch_kv(uint32_t sb, int bf, int b, int j0, int t) {
    const unsigned short* ks = g_k + ((size_t)(b * NN + j0)) * 64;
    #pragma unroll
    for (int kk = 0; kk < 4; kk++) {
        int idx = t + kk * 128;
        int row = idx >> 3, ch = idx & 7;
        cp16(sb + SK + bf * 8192 + row * 128 + ((ch ^ (row & 7)) << 4),
             ks + (size_t)row * 64 + ch * 8);
    }
    const unsigned short* hs = g_v + ((size_t)(b * NN + j0)) * 256;
    #pragma unroll
    for (int kk = 0; kk < 16; kk++) {
        int idx = t + kk * 128;
        int row = idx >> 5, ch = idx & 31;
        uint32_t off = row * 512 + (((ch & 24) | ((ch ^ row) & 7)) << 4);
        cp16(sb + SV + bf * 32768 + off, hs + (size_t)row * 256 + ch * 8);
    }
}

// =====================================================================
// fp16 mma.sync flash attention, 4 warps / TI=64 / 2 CTAs per SM.
// Per-warp code identical to the validated round-6/7 loop.
// =====================================================================
__global__ __launch_bounds__(128, 2) void attn_kernel(
    const float* __restrict__ x, float* __restrict__ out)
{
    extern __shared__ char smem[];
    const uint32_t sb = smem_u32(smem);
    const int t = threadIdx.x, lane = t & 31, w = t >> 5;
    const int b = blockIdx.y, i0 = blockIdx.x * TI;
    const int rr = lane >> 2, qd = lane & 3;
    const int l7 = lane & 7, lm8 = ((lane >> 3) & 1) * 8, lhi = lane >> 4, lm4 = lane >> 3;

    // ---- prefetch Q tile + first phase-1 K tile ----
    {
        const unsigned short* qs = g_q + ((size_t)(b * NN + i0)) * 64;
        #pragma unroll
        for (int kk = 0; kk < 4; kk++) {
            int idx = t + kk * 128;
            int row = idx >> 3, ch = idx & 7;
            cp16(sb + SQ + row * 128 + ((ch ^ (row & 7)) << 4),
                 qs + (size_t)row * 64 + ch * 8);
        }
        prefetch_k256(sb, 0, b, 0, t);
        cp_commit();
    }
    cp_wait0();
    __syncthreads();

    // ---- resident Q fragments (hi/lo, 2 k-chunks) ----
    uint32_t qh[2][4], ql[2][4];
    #pragma unroll
    for (int kc = 0; kc < 2; kc++) {
        int row = w * 16 + l7 + lm8;
        int chh = 2 * kc + lhi;
        ldsm4(qh[kc], sb + SQ + row * 128 + ((chh ^ (row & 7)) << 4));
        ldsm4(ql[kc], sb + SQ + row * 128 + (((chh + 4) ^ (row & 7)) << 4));
    }

    // ================= PHASE 1: row max (16 big tiles) =================
    float mx0 = -1e30f, mx1 = -1e30f;
    for (int it = 0; it < NSTEPS1; it++) {
        const int bf = it & 1;
        if (it > 0) { cp_wait0(); __syncthreads(); }
        if (it + 1 < NSTEPS1) { prefetch_k256(sb, bf ^ 1, b, (it + 1) * TJ1, t); cp_commit(); }
        const uint32_t kb = sb + SV + bf * 16384;
        #pragma unroll
        for (int hb = 0; hb < 32; hb++) {
            float S[4] = {0.f, 0.f, 0.f, 0.f};
            int krow = hb * 8 + l7;
            uint32_t a = kb + krow * 64 + ((lm4 ^ ((krow >> 1) & 3)) << 4);
            uint32_t kh4[4];
            ldsm4(kh4, a);
            mma16816(S, qh[0], kh4[0], kh4[1]);
            mma16816(S, qh[1], kh4[2], kh4[3]);
            mx0 = fmaxf(mx0, fmaxf(S[0], S[1]));
            mx1 = fmaxf(mx1, fmaxf(S[2], S[3]));
        }
    }
    mx0 = fmaxf(mx0, __shfl_xor_sync(0xffffffffu, mx0, 1));
    mx0 = fmaxf(mx0, __shfl_xor_sync(0xffffffffu, mx0, 2));
    mx1 = fmaxf(mx1, __shfl_xor_sync(0xffffffffu, mx1, 1));
    mx1 = fmaxf(mx1, __shfl_xor_sync(0xffffffffu, mx1, 2));

    // ================= PHASE 2: attention =================
    float O[32][4];
    #pragma unroll
    for (int i = 0; i < 32; i++)
        #pragma unroll
        for (int j = 0; j < 4; j++) O[i][j] = 0.f;
    float rs0 = 0.f, rs1 = 0.f;

    __syncthreads();          // all phase-1 reads of SV region done
    prefetch_kv(sb, 0, b, 0, t);
    cp_commit();
    cp_wait0();
    __syncthreads();

    for (int st = 0; st < NSTEPS; st++) {
        const int bf = st & 1;
        if (st > 0) { cp_wait0(); __syncthreads(); }
        if (st + 1 < NSTEPS) { prefetch_kv(sb, bf ^ 1, b, (st + 1) * TJ, t); cp_commit(); }

        const uint32_t kbase = sb + SK + bf * 8192;
        const uint32_t vbase = sb + SV + bf * 32768;

        #pragma unroll
        for (int kc = 0; kc < 4; kc++) {
            // ---- S for j-blocks 2kc, 2kc+1 (3-product hi/lo) ----
            float S[2][4];
            #pragma unroll
            for (int h = 0; h < 2; h++) {
                S[h][0] = S[h][1] = S[h][2] = S[h][3] = 0.f;
                int krow = (2 * kc + h) * 8 + l7;
                int swk = (krow & 7);
                uint32_t kh4[4], kl4[4];
                ldsm4(kh4, kbase + krow * 128 + ((lm4 ^ swk) << 4));
                ldsm4(kl4, kbase + krow * 128 + (((lm4 + 4) ^ swk) << 4));
                mma16816(S[h], qh[0], kh4[0], kh4[1]);
                mma16816(S[h], qh[1], kh4[2], kh4[3]);
                mma16816(S[h], qh[0], kl4[0], kl4[1]);
                mma16816(S[h], qh[1], kl4[2], kl4[3]);
                mma16816(S[h], ql[0], kh4[0], kh4[1]);
                mma16816(S[h], ql[1], kh4[2], kh4[3]);
            }

            // ---- p = exp(s - m), fp16 pack ----
            uint32_t pah[4];
            #pragma unroll
            for (int h = 0; h < 2; h++) {
                float e0 = __expf(S[h][0] - mx0), e1 = __expf(S[h][1] - mx0);
                float e2 = __expf(S[h][2] - mx1), e3 = __expf(S[h][3] - mx1);
                rs0 += e0 + e1;
                rs1 += e2 + e3;
                pah[h * 2]     = packh(e0, e1);
                pah[h * 2 + 1] = packh(e2, e3);
            }

            // ---- O += P @ V (single fp16 product, 32 channel-blocks) ----
            int vrow = kc * 16 + l7 + lm8;
            uint32_t vroff = vbase + vrow * 512;
            int swv = (vrow & 7);
            #pragma unroll
            for (int vb = 0; vb < 16; vb++) {
                int ch = vb * 2 + lhi;
                uint32_t a = vroff + ((((ch & 24) | ((ch ^ swv) & 7))) << 4);
                uint32_t vh4[4];
                ldsm4t(vh4, a);
                mma16816(O[2 * vb],     pah, vh4[0], vh4[1]);
                mma16816(O[2 * vb + 1], pah, vh4[2], vh4[3]);
            }
        }
    }

    // ---- row-sum reduce + epilogue (O/l + residual) ----
    rs0 += __shfl_xor_sync(0xffffffffu, rs0, 1);
    rs0 += __shfl_xor_sync(0xffffffffu, rs0, 2);
    rs1 += __shfl_xor_sync(0xffffffffu, rs1, 1);
    rs1 += __shfl_xor_sync(0xffffffffu, rs1, 2);
    const float li0 = 1.0f / rs0, li1 = 1.0f / rs1;

    const int ng = i0 + w * 16 + rr;
    #pragma unroll
    for (int nb = 0; nb < 32; nb++) {
        int c = nb * 8 + qd * 2;
        size_t g = ((size_t)b * NC + c) * NN + ng;
        out[g]          = O[nb][0] * li0 + x[g];
        out[g + NN]     = O[nb][1] * li0 + x[g + NN];
        out[g + 8]      = O[nb][2] * li1 + x[g + 8];
        out[g + 8 + NN] = O[nb][3] * li1 + x[g + 8 + NN];
    }
}

// =====================================================================
// Fused Q+K projection, cp.async pipelined x, reg-staged W tiles.
// =====================================================================
__global__ __launch_bounds__(256) void proj_qk2(
    const float* __restrict__ x,
    const float* __restrict__ Wq, const float* __restrict__ bq,
    const float* __restrict__ Wk, const float* __restrict__ bk,
    unsigned short* __restrict__ oq, unsigned short* __restrict__ ok)
{
    __shared__ float xs[2][32][64];
    __shared__ float wqs[2][32][34];
    __shared__ float wks[2][32][34];
    const int b  = blockIdx.z;
    const int n0 = blockIdx.x * 64;
    const int t  = threadIdx.x;
    const int go = t & 7, gn = t >> 3;
    const uint32_t sbx = smem_u32(&xs[0][0][0]);

    unsigned long long aq[2][2], ak[2][2];
    #pragma unroll
    for (int rp = 0; rp < 2; rp++) {
        aq[rp][0] = aq[rp][1] = 0ull;
        ak[rp][0] = ak[rp][1] = 0ull;
    }

    const float* xb = x + (size_t)b * NC * NN + n0;
    const int xcc = t >> 3, xnn = (t & 7) * 8;          // x tile: 2 cp16 per thread
    const int wo = t >> 3, wc4 = (t & 7) * 4;           // W slice: 1 float4 per W per thread

    // ---- prologue: x0 via cp.async, W0 direct ----
    {
        const float* src = xb + (size_t)xcc * NN + xnn;
        cp16(sbx + (0 * 2048 + xcc * 64 + xnn) * 4, src);
        cp16(sbx + (0 * 2048 + xcc * 64 + xnn + 4) * 4, src + 4);
        cp_commit();
        float4 q0 = *(const float4*)(Wq + (size_t)wo * NC + wc4);
        float4 k0 = *(const float4*)(Wk + (size_t)wo * NC + wc4);
        wqs[0][wc4 + 0][wo] = q0.x; wqs[0][wc4 + 1][wo] = q0.y;
        wqs[0][wc4 + 2][wo] = q0.z; wqs[0][wc4 + 3][wo] = q0.w;
        wks[0][wc4 + 0][wo] = k0.x; wks[0][wc4 + 1][wo] = k0.y;
        wks[0][wc4 + 2][wo] = k0.z; wks[0][wc4 + 3][wo] = k0.w;
    }

    for (int i = 0; i < 8; i++) {
        const int buf = i & 1;
        cp_wait0();
        __syncthreads();

        float4 qn, kn;
        if (i < 7) {
            int c0n = (i + 1) * 32;
            const float* src = xb + (size_t)(c0n + xcc) * NN + xnn;
            cp16(sbx + ((buf ^ 1) * 2048 + xcc * 64 + xnn) * 4, src);
            cp16(sbx + ((buf ^ 1) * 2048 + xcc * 64 + xnn + 4) * 4, src + 4);
            cp_commit();
            qn = *(const float4*)(Wq + (size_t)wo * NC + c0n + wc4);
            kn = *(const float4*)(Wk + (size_t)wo * NC + c0n + wc4);
        }

        #pragma unroll
        for (int cc = 0; cc < 32; cc++) {
            float x0 = xs[buf][cc][gn * 2], x1 = xs[buf][cc][gn * 2 + 1];
            unsigned long long xx0 = pack2(x0, x0), xx1 = pack2(x1, x1);
            #pragma unroll
            for (int rp = 0; rp < 2; rp++) {
                unsigned long long wq2 = *(const unsigned long long*)&wqs[buf][cc][go * 4 + rp * 2];
                fma2(aq[rp][0], wq2, xx0);
                fma2(aq[rp][1], wq2, xx1);
                unsigned long long wk2 = *(const unsigned long long*)&wks[buf][cc][go * 4 + rp * 2];
                fma2(ak[rp][0], wk2, xx0);
                fma2(ak[rp][1], wk2, xx1);
            }
        }

        if (i < 7) {
            wqs[buf ^ 1][wc4 + 0][wo] = qn.x; wqs[buf ^ 1][wc4 + 1][wo] = qn.y;
            wqs[buf ^ 1][wc4 + 2][wo] = qn.z; wqs[buf ^ 1][wc4 + 3][wo] = qn.w;
            wks[buf ^ 1][wc4 + 0][wo] = kn.x; wks[buf ^ 1][wc4 + 1][wo] = kn.y;
            wks[buf ^ 1][wc4 + 2][wo] = kn.z; wks[buf ^ 1][wc4 + 3][wo] = kn.w;
        }
        __syncthreads();
    }

    float bsq[4], bsk[4];
    #pragma unroll
    for (int r = 0; r < 4; r++) { bsq[r] = bq[go * 4 + r]; bsk[r] = bk[go * 4 + r]; }
    #pragma unroll
    for (int i = 0; i < 2; i++) {
        int n = n0 + gn * 2 + i;
        size_t base = ((size_t)(b * NN + n)) * 64 + go * 4;
        unsigned short h[4], l[4];
        #pragma unroll
        for (int rp = 0; rp < 2; rp++) {
            float2 f = unpack2(aq[rp][i]);
            float v0 = f.x + bsq[rp * 2], v1 = f.y + bsq[rp * 2 + 1];
            h[rp * 2] = f16h(v0);     l[rp * 2] = f16h(v0 - f16f(h[rp * 2]));
            h[rp * 2 + 1] = f16h(v1); l[rp * 2 + 1] = f16h(v1 - f16f(h[rp * 2 + 1]));
        }
        *(ushort4*)&oq[base]      = make_ushort4(h[0], h[1], h[2], h[3]);
        *(ushort4*)&oq[base + 32] = make_ushort4(l[0], l[1], l[2], l[3]);
        #pragma unroll
        for (int rp = 0; rp < 2; rp++) {
            float2 f = unpack2(ak[rp][i]);
            float v0 = f.x + bsk[rp * 2], v1 = f.y + bsk[rp * 2 + 1];
            h[rp * 2] = f16h(v0);     l[rp * 2] = f16h(v0 - f16f(h[rp * 2]));
            h[rp * 2 + 1] = f16h(v1); l[rp * 2 + 1] = f16h(v1 - f16f(h[rp * 2 + 1]));
        }
        *(ushort4*)&ok[base]      = make_ushort4(h[0], h[1], h[2], h[3]);
        *(ushort4*)&ok[base + 32] = make_ushort4(l[0], l[1], l[2], l[3]);
    }
}

// =====================================================================
// Projection V, cp.async pipelined x, reg-staged W tiles.
// =====================================================================
__global__ __launch_bounds__(256) void proj_v(
    const float* __restrict__ x, const float* __restrict__ W,
    const float* __restrict__ bias, unsigned short* __restrict__ vh)
{
    __shared__ float xs[2][32][64];
    __shared__ float ws[2][32][66];
    const int b  = blockIdx.z;
    const int n0 = blockIdx.x * 64;
    const int o0 = blockIdx.y * 64;
    const int t  = threadIdx.x;
    const int gn = t & 15, go = t >> 4;
    const uint32_t sbx = smem_u32(&xs[0][0][0]);

    unsigned long long acc[2][4];
    #pragma unroll
    for (int rp = 0; rp < 2; rp++)
        #pragma unroll
        for (int i = 0; i < 4; i++) acc[rp][i] = 0ull;

    const float* xb = x + (size_t)b * NC * NN + n0;
    const int xcc = t >> 3, xnn = (t & 7) * 8;
    const int wo = t >> 2, wc8 = (t & 3) * 8;           // W slice: 2 float4 per thread

    {
        const float* src = xb + (size_t)xcc * NN + xnn;
        cp16(sbx + (0 * 2048 + xcc * 64 + xnn) * 4, src);
        cp16(sbx + (0 * 2048 + xcc * 64 + xnn + 4) * 4, src + 4);
        cp_commit();
        const float* sw = W + (size_t)(o0 + wo) * NC + wc8;
        float4 w0 = *(const float4*)sw, w1 = *(const float4*)(sw + 4);
        ws[0][wc8 + 0][wo] = w0.x; ws[0][wc8 + 1][wo] = w0.y;
        ws[0][wc8 + 2][wo] = w0.z; ws[0][wc8 + 3][wo] = w0.w;
        ws[0][wc8 + 4][wo] = w1.x; ws[0][wc8 + 5][wo] = w1.y;
        ws[0][wc8 + 6][wo] = w1.z; ws[0][wc8 + 7][wo] = w1.w;
    }

    for (int i = 0; i < 8; i++) {
        const int buf = i & 1;
        cp_wait0();
        __syncthreads();

        float4 w0n, w1n;
        if (i < 7) {
            int c0n = (i + 1) * 32;
            const float* src = xb + (size_t)(c0n + xcc) * NN + xnn;
            cp16(sbx + ((buf ^ 1) * 2048 + xcc * 64 + xnn) * 4, src);
            cp16(sbx + ((buf ^ 1) * 2048 + xcc * 64 + xnn + 4) * 4, src + 4);
            cp_commit();
            const float* sw = W + (size_t)(o0 + wo) * NC + c0n + wc8;
            w0n = *(const float4*)sw; w1n = *(const float4*)(sw + 4);
        }

        #pragma unroll
        for (int cc = 0; cc < 32; cc++) {
            float4 xv = *(const float4*)&xs[buf][cc][gn * 4];
            unsigned long long xx[4];
            xx[0] = pack2(xv.x, xv.x); xx[1] = pack2(xv.y, xv.y);
            xx[2] = pack2(xv.z, xv.z); xx[3] = pack2(xv.w, xv.w);
            #pragma unroll
            for (int rp = 0; rp < 2; rp++) {
                unsigned long long w2 = *(const unsigned long long*)&ws[buf][cc][go * 4 + rp * 2];
                fma2(acc[rp][0], w2, xx[0]);
                fma2(acc[rp][1], w2, xx[1]);
                fma2(acc[rp][2], w2, xx[2]);
                fma2(acc[rp][3], w2, xx[3]);
            }
        }

        if (i < 7) {
            ws[buf ^ 1][wc8 + 0][wo] = w0n.x; ws[buf ^ 1][wc8 + 1][wo] = w0n.y;
            ws[buf ^ 1][wc8 + 2][wo] = w0n.z; ws[buf ^ 1][wc8 + 3][wo] = w0n.w;
            ws[buf ^ 1][wc8 + 4][wo] = w1n.x; ws[buf ^ 1][wc8 + 5][wo] = w1n.y;
            ws[buf ^ 1][wc8 + 6][wo] = w1n.z; ws[buf ^ 1][wc8 + 7][wo] = w1n.w;
        }
        __syncthreads();
    }

    float bs[4];
    #pragma unroll
    for (int r = 0; r < 4; r++) bs[r] = bias[o0 + go * 4 + r];
    #pragma unroll
    for (int i = 0; i < 4; i++) {
        int n = n0 + gn * 4 + i;
        unsigned short h[4];
        #pragma unroll
        for (int rp = 0; rp < 2; rp++) {
            float2 f = unpack2(acc[rp][i]);
            h[rp * 2]     = f16h(f.x + bs[rp * 2]);
            h[rp * 2 + 1] = f16h(f.y + bs[rp * 2 + 1]);
        }
        size_t base = ((size_t)(b * NN + n)) * 256 + o0 + go * 4;
        *(ushort4*)&vh[base] = make_ushort4(h[0], h[1], h[2], h[3]);
    }
}

// =====================================================================
extern "C" void kernel_launch(void* const* d_in, const int* in_sizes, int n_in,
                              void* d_out, int out_size)
{
    const float* x  = (const float*)d_in[0];
    const float* Wq = (const float*)d_in[1];
    const float* bq = (const float*)d_in[2];
    const float* Wk = (const float*)d_in[3];
    const float* bk = (const float*)d_in[4];
    const float* Wv = (const float*)d_in[5];
    const float* bv = (const float*)d_in[6];
    float* out = (float*)d_out;

    unsigned short *pq, *pk, *pv;
    cudaGetSymbolAddress((void**)&pq, g_q);
    cudaGetSymbolAddress((void**)&pk, g_k);
    cudaGetSymbolAddress((void**)&pv, g_v);

    cudaFuncSetAttribute(attn_kernel, cudaFuncAttributeMaxDynamicSharedMemorySize, SMEMB);

    proj_qk2<<<dim3(NN / 64, 1, NB), 256>>>(x, Wq, bq, Wk, bk, pq, pk);
    proj_v<<<dim3(NN / 64, NC / 64, NB), 256>>>(x, Wv, bv, pv);
    attn_kernel<<<dim3(NN / TI, NB), 128, SMEMB>>>(x, out);
}

// round 9
// speedup vs baseline: 1.9707x; 1.0672x over previous
#include <cuda_runtime.h>
#include <cuda_fp16.h>
#include <cstdint>

#define NB 4
#define NC 256
#define NN 4096
#define TI 128
#define TJ 64
#define NSTEPS (NN / TJ)
#define TJ1 256
#define NSTEPS1 (NN / TJ1)

// ---------------- device scratch (allocation-free) ----------------
__device__ unsigned short g_q[(size_t)NB * NN * 64];     // [b][n][32hi|32lo] fp16
__device__ unsigned short g_k[(size_t)NB * NN * 64];
__device__ unsigned short g_v[(size_t)NB * NN * 256];    // [b][n][c] fp16

// ---------------- attn SMEM layout (bytes) ----------------
#define SQ 0                       // 128 rows x 128B = 16384
#define SK 16384                   // + bf*8192 (64 rows x 128B)
#define SV 32768                   // + bf*32768 ; 64 j-rows x 512B
                                   // (phase 1 reuses SV region: 2 x 16384 K-hi tiles)
#define SMEMB (32768 + 2 * 32768)  // 98304

// ---------------- PTX helpers ----------------
__device__ __forceinline__ uint32_t smem_u32(const void* p) {
    uint32_t a;
    asm("{ .reg .u64 t; cvta.to.shared.u64 t, %1; cvt.u32.u64 %0, t; }" : "=r"(a) : "l"(p));
    return a;
}
__device__ __forceinline__ void cp16(uint32_t dst, const void* src) {
    asm volatile("cp.async.cg.shared.global [%0], [%1], 16;" :: "r"(dst), "l"(src));
}
__device__ __forceinline__ void cp_commit() { asm volatile("cp.async.commit_group;" ::: "memory"); }
__device__ __forceinline__ void cp_wait0()  { asm volatile("cp.async.wait_group 0;" ::: "memory"); }

__device__ __forceinline__ void ldsm4(uint32_t* r, uint32_t a) {
    asm volatile("ldmatrix.sync.aligned.m8n8.x4.shared.b16 {%0,%1,%2,%3}, [%4];"
        : "=r"(r[0]), "=r"(r[1]), "=r"(r[2]), "=r"(r[3]) : "r"(a));
}
__device__ __forceinline__ void ldsm4t(uint32_t* r, uint32_t a) {
    asm volatile("ldmatrix.sync.aligned.m8n8.x4.trans.shared.b16 {%0,%1,%2,%3}, [%4];"
        : "=r"(r[0]), "=r"(r[1]), "=r"(r[2]), "=r"(r[3]) : "r"(a));
}
__device__ __forceinline__ void mma16816(float* d, const uint32_t* a, uint32_t b0, uint32_t b1) {
    asm volatile("mma.sync.aligned.m16n8k16.row.col.f32.f16.f16.f32 "
        "{%0,%1,%2,%3}, {%4,%5,%6,%7}, {%8,%9}, {%0,%1,%2,%3};"
        : "+f"(d[0]), "+f"(d[1]), "+f"(d[2]), "+f"(d[3])
        : "r"(a[0]), "r"(a[1]), "r"(a[2]), "r"(a[3]), "r"(b0), "r"(b1));
}
// pack: first arg -> low half, second -> high half
__device__ __forceinline__ uint32_t packh(float lo, float hi) {
    uint32_t r;
    asm("cvt.rn.f16x2.f32 %0, %1, %2;" : "=r"(r) : "f"(hi), "f"(lo));
    return r;
}
__device__ __forceinline__ unsigned short f16h(float v) {
    __half h = __float2half_rn(v);
    return *reinterpret_cast<unsigned short*>(&h);
}
__device__ __forceinline__ float f16f(unsigned short u) {
    __half h = *reinterpret_cast<__half*>(&u);
    return __half2float(h);
}
// ---- packed fp32x2 (FFMA2) ----
__device__ __forceinline__ unsigned long long pack2(float x, float y) {
    unsigned long long r;
    asm("mov.b64 %0, {%1, %2};" : "=l"(r) : "f"(x), "f"(y));
    return r;
}
__device__ __forceinline__ void fma2(unsigned long long& a, unsigned long long b, unsigned long long c) {
    asm("fma.rn.f32x2 %0, %1, %2, %0;" : "+l"(a) : "l"(b), "l"(c));
}
__device__ __forceinline__ float2 unpack2(unsigned long long v) {
    float x, y;
    asm("mov.b64 {%0, %1}, %2;" : "=f"(x), "=f"(y) : "l"(v));
    return make_float2(x, y);
}

// ---------------- attn prefetchers (256 threads) ----------------
// phase 1: K hi-plane, 256 rows x 64B, swizzled for 64B-row ldsm
__device__ __forceinline__ void prefetch_k256(uint32_t sb, int bf, int b, int j0, int t) {
    #pragma unroll
    for (int kk = 0; kk < 4; kk++) {
        int idx = t + kk * 256;
        int row = idx >> 2, ch = idx & 3;
        cp16(sb + SV + bf * 16384 + row * 64 + ((ch ^ ((row >> 1) & 3)) << 4),
             g_k + ((size_t)(b * NN + j0 + row)) * 64 + ch * 8);
    }
}
// phase 2: full K (hi+lo) + V
__device__ __forceinline__ void prefetch_kv(uint32_t sb, int bf, int b, int j0, int t) {
    const unsigned short* ks = g_k + ((size_t)(b * NN + j0)) * 64;
    #pragma unroll
    for (int kk = 0; kk < 2; kk++) {
        int idx = t + kk * 256;
        int row = idx >> 3, ch = idx & 7;
        cp16(sb + SK + bf * 8192 + row * 128 + ((ch ^ (row & 7)) << 4),
             ks + (size_t)row * 64 + ch * 8);
    }
    const unsigned short* hs = g_v + ((size_t)(b * NN + j0)) * 256;
    #pragma unroll
    for (int kk = 0; kk < 8; kk++) {
        int idx = t + kk * 256;
        int row = idx >> 5, ch = idx & 31;
        uint32_t off = row * 512 + (((ch & 24) | ((ch ^ row) & 7)) << 4);
        cp16(sb + SV + bf * 32768 + off, hs + (size_t)row * 256 + ch * 8);
    }
}

// =====================================================================
// fp16 mma.sync flash attention (validated round-7 shape: TI=128, 8 warps)
// =====================================================================
__global__ __launch_bounds__(256, 1) void attn_kernel(
    const float* __restrict__ x, float* __restrict__ out)
{
    extern __shared__ char smem[];
    const uint32_t sb = smem_u32(smem);
    const int t = threadIdx.x, lane = t & 31, w = t >> 5;
    const int b = blockIdx.y, i0 = blockIdx.x * TI;
    const int rr = lane >> 2, qd = lane & 3;
    const int l7 = lane & 7, lm8 = ((lane >> 3) & 1) * 8, lhi = lane >> 4, lm4 = lane >> 3;

    // ---- prefetch Q tile + first phase-1 K tile ----
    {
        const unsigned short* qs = g_q + ((size_t)(b * NN + i0)) * 64;
        #pragma unroll
        for (int kk = 0; kk < 4; kk++) {
            int idx = t + kk * 256;
            int row = idx >> 3, ch = idx & 7;
            cp16(sb + SQ + row * 128 + ((ch ^ (row & 7)) << 4),
                 qs + (size_t)row * 64 + ch * 8);
        }
        prefetch_k256(sb, 0, b, 0, t);
        cp_commit();
    }
    cp_wait0();
    __syncthreads();

    // ---- resident Q fragments (hi/lo, 2 k-chunks) ----
    uint32_t qh[2][4], ql[2][4];
    #pragma unroll
    for (int kc = 0; kc < 2; kc++) {
        int row = w * 16 + l7 + lm8;
        int chh = 2 * kc + lhi;
        ldsm4(qh[kc], sb + SQ + row * 128 + ((chh ^ (row & 7)) << 4));
        ldsm4(ql[kc], sb + SQ + row * 128 + (((chh + 4) ^ (row & 7)) << 4));
    }

    // ================= PHASE 1: row max (16 big tiles) =================
    float mx0 = -1e30f, mx1 = -1e30f;
    for (int it = 0; it < NSTEPS1; it++) {
        const int bf = it & 1;
        if (it > 0) { cp_wait0(); __syncthreads(); }
        if (it + 1 < NSTEPS1) { prefetch_k256(sb, bf ^ 1, b, (it + 1) * TJ1, t); cp_commit(); }
        const uint32_t kb = sb + SV + bf * 16384;
        #pragma unroll
        for (int hb = 0; hb < 32; hb++) {
            float S[4] = {0.f, 0.f, 0.f, 0.f};
            int krow = hb * 8 + l7;
            uint32_t a = kb + krow * 64 + ((lm4 ^ ((krow >> 1) & 3)) << 4);
            uint32_t kh4[4];
            ldsm4(kh4, a);
            mma16816(S, qh[0], kh4[0], kh4[1]);
            mma16816(S, qh[1], kh4[2], kh4[3]);
            mx0 = fmaxf(mx0, fmaxf(S[0], S[1]));
            mx1 = fmaxf(mx1, fmaxf(S[2], S[3]));
        }
    }
    mx0 = fmaxf(mx0, __shfl_xor_sync(0xffffffffu, mx0, 1));
    mx0 = fmaxf(mx0, __shfl_xor_sync(0xffffffffu, mx0, 2));
    mx1 = fmaxf(mx1, __shfl_xor_sync(0xffffffffu, mx1, 1));
    mx1 = fmaxf(mx1, __shfl_xor_sync(0xffffffffu, mx1, 2));

    // ================= PHASE 2: attention =================
    float O[32][4];
    #pragma unroll
    for (int i = 0; i < 32; i++)
        #pragma unroll
        for (int j = 0; j < 4; j++) O[i][j] = 0.f;
    float rs0 = 0.f, rs1 = 0.f;

    __syncthreads();          // all phase-1 reads of SV region done
    prefetch_kv(sb, 0, b, 0, t);
    cp_commit();
    cp_wait0();
    __syncthreads();

    for (int st = 0; st < NSTEPS; st++) {
        const int bf = st & 1;
        if (st > 0) { cp_wait0(); __syncthreads(); }
        if (st + 1 < NSTEPS) { prefetch_kv(sb, bf ^ 1, b, (st + 1) * TJ, t); cp_commit(); }

        const uint32_t kbase = sb + SK + bf * 8192;
        const uint32_t vbase = sb + SV + bf * 32768;

        #pragma unroll
        for (int kc = 0; kc < 4; kc++) {
            // ---- S for j-blocks 2kc, 2kc+1 (3-product hi/lo) ----
            float S[2][4];
            #pragma unroll
            for (int h = 0; h < 2; h++) {
                S[h][0] = S[h][1] = S[h][2] = S[h][3] = 0.f;
                int krow = (2 * kc + h) * 8 + l7;
                int swk = (krow & 7);
                uint32_t kh4[4], kl4[4];
                ldsm4(kh4, kbase + krow * 128 + ((lm4 ^ swk) << 4));
                ldsm4(kl4, kbase + krow * 128 + (((lm4 + 4) ^ swk) << 4));
                mma16816(S[h], qh[0], kh4[0], kh4[1]);
                mma16816(S[h], qh[1], kh4[2], kh4[3]);
                mma16816(S[h], qh[0], kl4[0], kl4[1]);
                mma16816(S[h], qh[1], kl4[2], kl4[3]);
                mma16816(S[h], ql[0], kh4[0], kh4[1]);
                mma16816(S[h], ql[1], kh4[2], kh4[3]);
            }

            // ---- p = exp(s - m), fp16 pack ----
            uint32_t pah[4];
            #pragma unroll
            for (int h = 0; h < 2; h++) {
                float e0 = __expf(S[h][0] - mx0), e1 = __expf(S[h][1] - mx0);
                float e2 = __expf(S[h][2] - mx1), e3 = __expf(S[h][3] - mx1);
                rs0 += e0 + e1;
                rs1 += e2 + e3;
                pah[h * 2]     = packh(e0, e1);
                pah[h * 2 + 1] = packh(e2, e3);
            }

            // ---- O += P @ V (single fp16 product, 32 channel-blocks) ----
            int vrow = kc * 16 + l7 + lm8;
            uint32_t vroff = vbase + vrow * 512;
            int swv = (vrow & 7);
            #pragma unroll
            for (int vb = 0; vb < 16; vb++) {
                int ch = vb * 2 + lhi;
                uint32_t a = vroff + ((((ch & 24) | ((ch ^ swv) & 7))) << 4);
                uint32_t vh4[4];
                ldsm4t(vh4, a);
                mma16816(O[2 * vb],     pah, vh4[0], vh4[1]);
                mma16816(O[2 * vb + 1], pah, vh4[2], vh4[3]);
            }
        }
    }

    // ---- row-sum reduce + epilogue (O/l + residual) ----
    rs0 += __shfl_xor_sync(0xffffffffu, rs0, 1);
    rs0 += __shfl_xor_sync(0xffffffffu, rs0, 2);
    rs1 += __shfl_xor_sync(0xffffffffu, rs1, 1);
    rs1 += __shfl_xor_sync(0xffffffffu, rs1, 2);
    const float li0 = 1.0f / rs0, li1 = 1.0f / rs1;

    const int ng = i0 + w * 16 + rr;
    #pragma unroll
    for (int nb = 0; nb < 32; nb++) {
        int c = nb * 8 + qd * 2;
        size_t g = ((size_t)b * NC + c) * NN + ng;
        out[g]          = O[nb][0] * li0 + x[g];
        out[g + NN]     = O[nb][1] * li0 + x[g + NN];
        out[g + 8]      = O[nb][2] * li1 + x[g + 8];
        out[g + 8 + NN] = O[nb][3] * li1 + x[g + 8 + NN];
    }
}

// =====================================================================
// Fused projections: grid.y 0-3 -> V o-tiles, grid.y 4 -> Q+K path.
// Both paths cp.async-pipelined; shared dynamic smem (34 KB union).
// =====================================================================
__device__ __forceinline__ void proj_qk_body(
    char* ps, const float* __restrict__ x,
    const float* __restrict__ Wq, const float* __restrict__ bq,
    const float* __restrict__ Wk, const float* __restrict__ bk,
    unsigned short* __restrict__ oq, unsigned short* __restrict__ ok,
    int b, int n0, int t)
{
    float (*xs)[32][64]  = (float (*)[32][64])ps;
    float (*wqs)[32][34] = (float (*)[32][34])(ps + 16384);
    float (*wks)[32][34] = (float (*)[32][34])(ps + 16384 + 8704);
    const int go = t & 7, gn = t >> 3;
    const uint32_t sbx = smem_u32(ps);

    unsigned long long aq[2][2], ak[2][2];
    #pragma unroll
    for (int rp = 0; rp < 2; rp++) {
        aq[rp][0] = aq[rp][1] = 0ull;
        ak[rp][0] = ak[rp][1] = 0ull;
    }

    const float* xb = x + (size_t)b * NC * NN + n0;
    const int xcc = t >> 3, xnn = (t & 7) * 8;
    const int wo = t >> 3, wc4 = (t & 7) * 4;

    {
        const float* src = xb + (size_t)xcc * NN + xnn;
        cp16(sbx + (xcc * 64 + xnn) * 4, src);
        cp16(sbx + (xcc * 64 + xnn + 4) * 4, src + 4);
        cp_commit();
        float4 q0 = *(const float4*)(Wq + (size_t)wo * NC + wc4);
        float4 k0 = *(const float4*)(Wk + (size_t)wo * NC + wc4);
        wqs[0][wc4 + 0][wo] = q0.x; wqs[0][wc4 + 1][wo] = q0.y;
        wqs[0][wc4 + 2][wo] = q0.z; wqs[0][wc4 + 3][wo] = q0.w;
        wks[0][wc4 + 0][wo] = k0.x; wks[0][wc4 + 1][wo] = k0.y;
        wks[0][wc4 + 2][wo] = k0.z; wks[0][wc4 + 3][wo] = k0.w;
    }

    for (int i = 0; i < 8; i++) {
        const int buf = i & 1;
        cp_wait0();
        __syncthreads();

        float4 qn, kn;
        if (i < 7) {
            int c0n = (i + 1) * 32;
            const float* src = xb + (size_t)(c0n + xcc) * NN + xnn;
            cp16(sbx + ((buf ^ 1) * 2048 + xcc * 64 + xnn) * 4, src);
            cp16(sbx + ((buf ^ 1) * 2048 + xcc * 64 + xnn + 4) * 4, src + 4);
            cp_commit();
            qn = *(const float4*)(Wq + (size_t)wo * NC + c0n + wc4);
            kn = *(const float4*)(Wk + (size_t)wo * NC + c0n + wc4);
        }

        #pragma unroll
        for (int cc = 0; cc < 32; cc++) {
            float x0 = xs[buf][cc][gn * 2], x1 = xs[buf][cc][gn * 2 + 1];
            unsigned long long xx0 = pack2(x0, x0), xx1 = pack2(x1, x1);
            #pragma unroll
            for (int rp = 0; rp < 2; rp++) {
                unsigned long long wq2 = *(const unsigned long long*)&wqs[buf][cc][go * 4 + rp * 2];
                fma2(aq[rp][0], wq2, xx0);
                fma2(aq[rp][1], wq2, xx1);
                unsigned long long wk2 = *(const unsigned long long*)&wks[buf][cc][go * 4 + rp * 2];
                fma2(ak[rp][0], wk2, xx0);
                fma2(ak[rp][1], wk2, xx1);
            }
        }

        if (i < 7) {
            wqs[buf ^ 1][wc4 + 0][wo] = qn.x; wqs[buf ^ 1][wc4 + 1][wo] = qn.y;
            wqs[buf ^ 1][wc4 + 2][wo] = qn.z; wqs[buf ^ 1][wc4 + 3][wo] = qn.w;
            wks[buf ^ 1][wc4 + 0][wo] = kn.x; wks[buf ^ 1][wc4 + 1][wo] = kn.y;
            wks[buf ^ 1][wc4 + 2][wo] = kn.z; wks[buf ^ 1][wc4 + 3][wo] = kn.w;
        }
        __syncthreads();
    }

    float bsq[4], bsk[4];
    #pragma unroll
    for (int r = 0; r < 4; r++) { bsq[r] = bq[go * 4 + r]; bsk[r] = bk[go * 4 + r]; }
    #pragma unroll
    for (int i = 0; i < 2; i++) {
        int n = n0 + gn * 2 + i;
        size_t base = ((size_t)(b * NN + n)) * 64 + go * 4;
        unsigned short h[4], l[4];
        #pragma unroll
        for (int rp = 0; rp < 2; rp++) {
            float2 f = unpack2(aq[rp][i]);
            float v0 = f.x + bsq[rp * 2], v1 = f.y + bsq[rp * 2 + 1];
            h[rp * 2] = f16h(v0);     l[rp * 2] = f16h(v0 - f16f(h[rp * 2]));
            h[rp * 2 + 1] = f16h(v1); l[rp * 2 + 1] = f16h(v1 - f16f(h[rp * 2 + 1]));
        }
        *(ushort4*)&oq[base]      = make_ushort4(h[0], h[1], h[2], h[3]);
        *(ushort4*)&oq[base + 32] = make_ushort4(l[0], l[1], l[2], l[3]);
        #pragma unroll
        for (int rp = 0; rp < 2; rp++) {
            float2 f = unpack2(ak[rp][i]);
            float v0 = f.x + bsk[rp * 2], v1 = f.y + bsk[rp * 2 + 1];
            h[rp * 2] = f16h(v0);     l[rp * 2] = f16h(v0 - f16f(h[rp * 2]));
            h[rp * 2 + 1] = f16h(v1); l[rp * 2 + 1] = f16h(v1 - f16f(h[rp * 2 + 1]));
        }
        *(ushort4*)&ok[base]      = make_ushort4(h[0], h[1], h[2], h[3]);
        *(ushort4*)&ok[base + 32] = make_ushort4(l[0], l[1], l[2], l[3]);
    }
}

__device__ __forceinline__ void proj_v_body(
    char* ps, const float* __restrict__ x, const float* __restrict__ W,
    const float* __restrict__ bias, unsigned short* __restrict__ vh,
    int b, int n0, int o0, int t)
{
    float (*xs)[32][64] = (float (*)[32][64])ps;
    float (*ws)[32][66] = (float (*)[32][66])(ps + 16384);
    const int gn = t & 15, go = t >> 4;
    const uint32_t sbx = smem_u32(ps);

    unsigned long long acc[2][4];
    #pragma unroll
    for (int rp = 0; rp < 2; rp++)
        #pragma unroll
        for (int i = 0; i < 4; i++) acc[rp][i] = 0ull;

    const float* xb = x + (size_t)b * NC * NN + n0;
    const int xcc = t >> 3, xnn = (t & 7) * 8;
    const int wo = t >> 2, wc8 = (t & 3) * 8;

    {
        const float* src = xb + (size_t)xcc * NN + xnn;
        cp16(sbx + (xcc * 64 + xnn) * 4, src);
        cp16(sbx + (xcc * 64 + xnn + 4) * 4, src + 4);
        cp_commit();
        const float* sw = W + (size_t)(o0 + wo) * NC + wc8;
        float4 w0 = *(const float4*)sw, w1 = *(const float4*)(sw + 4);
        ws[0][wc8 + 0][wo] = w0.x; ws[0][wc8 + 1][wo] = w0.y;
        ws[0][wc8 + 2][wo] = w0.z; ws[0][wc8 + 3][wo] = w0.w;
        ws[0][wc8 + 4][wo] = w1.x; ws[0][wc8 + 5][wo] = w1.y;
        ws[0][wc8 + 6][wo] = w1.z; ws[0][wc8 + 7][wo] = w1.w;
    }

    for (int i = 0; i < 8; i++) {
        const int buf = i & 1;
        cp_wait0();
        __syncthreads();

        float4 w0n, w1n;
        if (i < 7) {
            int c0n = (i + 1) * 32;
            const float* src = xb + (size_t)(c0n + xcc) * NN + xnn;
            cp16(sbx + ((buf ^ 1) * 2048 + xcc * 64 + xnn) * 4, src);
            cp16(sbx + ((buf ^ 1) * 2048 + xcc * 64 + xnn + 4) * 4, src + 4);
            cp_commit();
            const float* sw = W + (size_t)(o0 + wo) * NC + c0n + wc8;
            w0n = *(const float4*)sw; w1n = *(const float4*)(sw + 4);
        }

        #pragma unroll
        for (int cc = 0; cc < 32; cc++) {
            float4 xv = *(const float4*)&xs[buf][cc][gn * 4];
            unsigned long long xx[4];
            xx[0] = pack2(xv.x, xv.x); xx[1] = pack2(xv.y, xv.y);
            xx[2] = pack2(xv.z, xv.z); xx[3] = pack2(xv.w, xv.w);
            #pragma unroll
            for (int rp = 0; rp < 2; rp++) {
                unsigned long long w2 = *(const unsigned long long*)&ws[buf][cc][go * 4 + rp * 2];
                fma2(acc[rp][0], w2, xx[0]);
                fma2(acc[rp][1], w2, xx[1]);
                fma2(acc[rp][2], w2, xx[2]);
                fma2(acc[rp][3], w2, xx[3]);
            }
        }

        if (i < 7) {
            ws[buf ^ 1][wc8 + 0][wo] = w0n.x; ws[buf ^ 1][wc8 + 1][wo] = w0n.y;
            ws[buf ^ 1][wc8 + 2][wo] = w0n.z; ws[buf ^ 1][wc8 + 3][wo] = w0n.w;
            ws[buf ^ 1][wc8 + 4][wo] = w1n.x; ws[buf ^ 1][wc8 + 5][wo] = w1n.y;
            ws[buf ^ 1][wc8 + 6][wo] = w1n.z; ws[buf ^ 1][wc8 + 7][wo] = w1n.w;
        }
        __syncthreads();
    }

    float bs[4];
    #pragma unroll
    for (int r = 0; r < 4; r++) bs[r] = bias[o0 + go * 4 + r];
    #pragma unroll
    for (int i = 0; i < 4; i++) {
        int n = n0 + gn * 4 + i;
        unsigned short h[4];
        #pragma unroll
        for (int rp = 0; rp < 2; rp++) {
            float2 f = unpack2(acc[rp][i]);
            h[rp * 2]     = f16h(f.x + bs[rp * 2]);
            h[rp * 2 + 1] = f16h(f.y + bs[rp * 2 + 1]);
        }
        size_t base = ((size_t)(b * NN + n)) * 256 + o0 + go * 4;
        *(ushort4*)&vh[base] = make_ushort4(h[0], h[1], h[2], h[3]);
    }
}

__global__ __launch_bounds__(256) void proj_fused(
    const float* __restrict__ x,
    const float* __restrict__ Wq, const float* __restrict__ bq,
    const float* __restrict__ Wk, const float* __restrict__ bk,
    const float* __restrict__ Wv, const float* __restrict__ bv,
    unsigned short* __restrict__ oq, unsigned short* __restrict__ ok,
    unsigned short* __restrict__ vh)
{
    extern __shared__ char ps[];
    const int b = blockIdx.z, n0 = blockIdx.x * 64, t = threadIdx.x;
    if (blockIdx.y < 4) {
        proj_v_body(ps, x, Wv, bv, vh, b, n0, blockIdx.y * 64, t);
    } else {
        proj_qk_body(ps, x, Wq, bq, Wk, bk, oq, ok, b, n0, t);
    }
}

// =====================================================================
extern "C" void kernel_launch(void* const* d_in, const int* in_sizes, int n_in,
                              void* d_out, int out_size)
{
    const float* x  = (const float*)d_in[0];
    const float* Wq = (const float*)d_in[1];
    const float* bq = (const float*)d_in[2];
    const float* Wk = (const float*)d_in[3];
    const float* bk = (const float*)d_in[4];
    const float* Wv = (const float*)d_in[5];
    const float* bv = (const float*)d_in[6];
    float* out = (float*)d_out;

    unsigned short *pq, *pk, *pv;
    cudaGetSymbolAddress((void**)&pq, g_q);
    cudaGetSymbolAddress((void**)&pk, g_k);
    cudaGetSymbolAddress((void**)&pv, g_v);

    cudaFuncSetAttribute(attn_kernel, cudaFuncAttributeMaxDynamicSharedMemorySize, SMEMB);

    const int PSMEM = 16384 + 2 * 16896;   // xs + max(wqs+wks, ws) rounded: 50176? no:
    // QK path: 16384 + 8704 + 8704 = 33792 ; V path: 16384 + 16896 = 33280 -> 33792
    proj_fused<<<dim3(NN / 64, 5, NB), 256, 33792>>>(x, Wq, bq, Wk, bk, Wv, bv, pq, pk, pv);
    attn_kernel<<<dim3(NN / TI, NB), 256, SMEMB>>>(x, out);
}